// round 1
// baseline (speedup 1.0000x reference)
#include <cuda_runtime.h>
#include <cuda_bf16.h>
#include <math.h>

// Problem constants
#define B_  2
#define T_  2048
#define E_  2048
#define H_  16
#define KVH_ 8
#define D_  128
#define ROWS_ (B_ * T_)            // 4096

// ---------------- scratch (device globals; no allocs allowed) ----------------
__device__ float g_q[(size_t)ROWS_ * H_ * D_];     // (B*T, H*D)   33.5 MB
__device__ float g_k[(size_t)ROWS_ * KVH_ * D_];   // (B*T, KVH*D) 16.8 MB
__device__ float g_v[(size_t)ROWS_ * KVH_ * D_];   // 16.8 MB
__device__ float g_o[(size_t)ROWS_ * H_ * D_];     // attention out 33.5 MB

// ---------------- SGEMM: C[M,N] = A[M,K] @ B[K,N], row-major --------------
// BM=BN=128, BK=16, TM=TN=8, 256 threads.
__global__ void __launch_bounds__(256) sgemm_kernel(
    int M, int N, int K,
    const float* __restrict__ A, const float* __restrict__ B,
    float* __restrict__ C)
{
    __shared__ float As[16][132];   // transposed A tile, padded
    __shared__ float Bs[16][132];   // B tile, padded

    const int tid = threadIdx.x;
    const int cRow = blockIdx.y, cCol = blockIdx.x;
    const int threadRow = tid >> 4;     // 0..15
    const int threadCol = tid & 15;     // 0..15

    A += (size_t)cRow * 128 * K;
    B += (size_t)cCol * 128;
    C += (size_t)cRow * 128 * N + (size_t)cCol * 128;

    const int aRow = tid >> 2;          // 0..63
    const int aCol = (tid & 3) * 4;     // 0,4,8,12
    const int bRow = tid >> 5;          // 0..7
    const int bCol = (tid & 31) * 4;    // 0..124

    float results[64];
#pragma unroll
    for (int i = 0; i < 64; i++) results[i] = 0.f;
    float regM[8], regN[8];

    for (int bk = 0; bk < K; bk += 16) {
#pragma unroll
        for (int off = 0; off < 128; off += 64) {
            float4 t4 = *(const float4*)(A + (size_t)(aRow + off) * K + aCol);
            As[aCol + 0][aRow + off] = t4.x;
            As[aCol + 1][aRow + off] = t4.y;
            As[aCol + 2][aRow + off] = t4.z;
            As[aCol + 3][aRow + off] = t4.w;
        }
#pragma unroll
        for (int off = 0; off < 16; off += 8) {
            *(float4*)(&Bs[bRow + off][bCol]) =
                *(const float4*)(B + (size_t)(bRow + off) * N + bCol);
        }
        __syncthreads();
        A += 16;
        B += (size_t)16 * N;

#pragma unroll
        for (int k = 0; k < 16; k++) {
#pragma unroll
            for (int m = 0; m < 8; m++) regM[m] = As[k][threadRow * 8 + m];
#pragma unroll
            for (int n = 0; n < 8; n++) regN[n] = Bs[k][threadCol * 8 + n];
#pragma unroll
            for (int m = 0; m < 8; m++)
#pragma unroll
                for (int n = 0; n < 8; n++)
                    results[m * 8 + n] = fmaf(regM[m], regN[n], results[m * 8 + n]);
        }
        __syncthreads();
    }

#pragma unroll
    for (int m = 0; m < 8; m++) {
#pragma unroll
        for (int n = 0; n < 8; n += 4) {
            float4 t4 = { results[m * 8 + n], results[m * 8 + n + 1],
                          results[m * 8 + n + 2], results[m * 8 + n + 3] };
            *(float4*)(C + (size_t)(threadRow * 8 + m) * N + threadCol * 8 + n) = t4;
        }
    }
}

// ---------------- RoPE (in place), matches jax fp32 reference ----------------
// X layout: rows = b*T + t (ROWS_), cols = nh*128. Pairs (2j, 2j+1).
__global__ void rope_kernel(float* __restrict__ X, int nh, int total)
{
    int idx = blockIdx.x * blockDim.x + threadIdx.x;
    if (idx >= total) return;
    int j = idx & 63;
    int rest = idx >> 6;
    int hh = rest % nh;
    int row = rest / nh;
    int t = row & (T_ - 1);

    float inv = 1.0f / powf(10000.0f, (float)j * (1.0f / 64.0f));
    float ang = (float)t * inv;
    float s, c;
    sincosf(ang, &s, &c);

    float* p = X + (size_t)row * (nh * D_) + hh * D_ + 2 * j;
    float x0 = p[0], x1 = p[1];
    p[0] = x0 * c - x1 * s;
    p[1] = x0 * s + x1 * c;
}

// ---------------- Flash attention (causal, GQA), fp32 -----------------------
// grid: (T/64, H, B), 256 threads. Br=Bc=64, D=128.
// smem: Qs[64][132], Ks[64][132], Vs[64][132], S[64][64], m/l/alpha[64]
#define QKV_PAD 132
#define FLASH_SMEM_FLOATS (3 * 64 * QKV_PAD + 64 * 64 + 3 * 64)

__global__ void __launch_bounds__(256, 1) flash_attn_kernel(
    const float* __restrict__ Q, const float* __restrict__ Kg,
    const float* __restrict__ Vg, float* __restrict__ O)
{
    extern __shared__ float sm[];
    float* Qs = sm;                       // 64*132
    float* Ks = Qs + 64 * QKV_PAD;
    float* Vs = Ks + 64 * QKV_PAD;
    float* S  = Vs + 64 * QKV_PAD;        // 64*64
    float* mrow = S + 64 * 64;
    float* lrow = mrow + 64;
    float* arow = lrow + 64;

    const int tid = threadIdx.x;
    const int qt = blockIdx.x, h = blockIdx.y, b = blockIdx.z;
    const int kvh = h >> 1;               // GQA: H/KVH = 2
    const int q0 = qt * 64;

    // load Q tile (64 rows x 128)
    {
        int r = tid >> 2, c0 = (tid & 3) * 8;
        const float4* src = (const float4*)(Q + (size_t)(b * T_ + q0 + r) * (H_ * D_) + h * D_) + c0;
        float4* dst = (float4*)(Qs + r * QKV_PAD) + c0;
#pragma unroll
        for (int i = 0; i < 8; i++) dst[i] = src[i];
    }
    if (tid < 64) { mrow[tid] = -INFINITY; lrow[tid] = 0.f; }

    float acc[32];
#pragma unroll
    for (int i = 0; i < 32; i++) acc[i] = 0.f;
    const int r  = tid >> 2;              // output row this thread owns
    const int dh = (tid & 3) * 32;        // output dim slice
    const float scale = 0.08838834764831845f; // 1/sqrt(128)

    for (int kt = 0; kt <= qt; kt++) {
        __syncthreads();   // protect Ks/Vs/S reuse from previous iteration
        // load K, V tiles
        {
            int rr = tid >> 2, c0 = (tid & 3) * 8;
            size_t gbase = (size_t)(b * T_ + kt * 64 + rr) * (KVH_ * D_) + kvh * D_;
            const float4* ksrc = (const float4*)(Kg + gbase) + c0;
            const float4* vsrc = (const float4*)(Vg + gbase) + c0;
            float4* kd = (float4*)(Ks + rr * QKV_PAD) + c0;
            float4* vd = (float4*)(Vs + rr * QKV_PAD) + c0;
#pragma unroll
            for (int i = 0; i < 8; i++) { kd[i] = ksrc[i]; vd[i] = vsrc[i]; }
        }
        __syncthreads();

        // scores: thread (tr, tc) computes rows {tr*4+i}, cols {tc + 16*jj}
        {
            const int tr = tid >> 4;      // 0..15
            const int tc = tid & 15;      // 0..15
            float s4[4][4];
#pragma unroll
            for (int i = 0; i < 4; i++)
#pragma unroll
                for (int jj = 0; jj < 4; jj++) s4[i][jj] = 0.f;

            const float* qb = Qs + (tr * 4) * QKV_PAD;
            for (int d = 0; d < 128; d++) {
                float kvv[4];
#pragma unroll
                for (int jj = 0; jj < 4; jj++)
                    kvv[jj] = Ks[(tc + 16 * jj) * QKV_PAD + d];
#pragma unroll
                for (int i = 0; i < 4; i++) {
                    float qv = qb[i * QKV_PAD + d];
#pragma unroll
                    for (int jj = 0; jj < 4; jj++)
                        s4[i][jj] = fmaf(qv, kvv[jj], s4[i][jj]);
                }
            }
            const bool diag = (kt == qt);
#pragma unroll
            for (int i = 0; i < 4; i++) {
                int gi = tr * 4 + i;
#pragma unroll
                for (int jj = 0; jj < 4; jj++) {
                    int gj = tc + 16 * jj;
                    float v = s4[i][jj] * scale;
                    if (diag && gj > gi) v = -1e30f;  // kt==qt => global: kt*64+gj > q0+gi
                    S[gi * 64 + gj] = v;
                }
            }
        }
        __syncthreads();

        // online softmax row update (threads 0..63, one row each)
        if (tid < 64) {
            float m_old = mrow[tid];
            float mx = m_old;
            float* srow = S + tid * 64;
#pragma unroll 8
            for (int j = 0; j < 64; j++) mx = fmaxf(mx, srow[j]);
            float sum = 0.f;
#pragma unroll 8
            for (int j = 0; j < 64; j++) {
                float p = __expf(srow[j] - mx);
                srow[j] = p;
                sum += p;
            }
            float al = __expf(m_old - mx);
            lrow[tid] = lrow[tid] * al + sum;
            mrow[tid] = mx;
            arow[tid] = al;
        }
        __syncthreads();

        // O accumulate: acc = acc*alpha + P @ V
        {
            float al = arow[r];
#pragma unroll
            for (int i = 0; i < 32; i++) acc[i] *= al;
            const float* srow = S + r * 64;
#pragma unroll 4
            for (int j = 0; j < 64; j++) {
                float p = srow[j];
                const float4* vr = (const float4*)(Vs + j * QKV_PAD + dh);
#pragma unroll
                for (int d4 = 0; d4 < 8; d4++) {
                    float4 vv = vr[d4];
                    acc[d4 * 4 + 0] = fmaf(p, vv.x, acc[d4 * 4 + 0]);
                    acc[d4 * 4 + 1] = fmaf(p, vv.y, acc[d4 * 4 + 1]);
                    acc[d4 * 4 + 2] = fmaf(p, vv.z, acc[d4 * 4 + 2]);
                    acc[d4 * 4 + 3] = fmaf(p, vv.w, acc[d4 * 4 + 3]);
                }
            }
        }
    }

    // epilogue: normalize and store
    {
        float inv_l = 1.f / lrow[r];
        float* dst = O + (size_t)(b * T_ + q0 + r) * (H_ * D_) + h * D_ + dh;
#pragma unroll
        for (int d4 = 0; d4 < 8; d4++) {
            float4 o4 = { acc[d4 * 4 + 0] * inv_l, acc[d4 * 4 + 1] * inv_l,
                          acc[d4 * 4 + 2] * inv_l, acc[d4 * 4 + 3] * inv_l };
            ((float4*)dst)[d4] = o4;
        }
    }
}

// -------------------------------- launch -------------------------------------
extern "C" void kernel_launch(void* const* d_in, const int* in_sizes, int n_in,
                              void* d_out, int out_size)
{
    const float* x  = (const float*)d_in[0];
    // d_in[1] = mask (int32 causal tril) — implied by causal loop, unused
    const float* wq = (const float*)d_in[2];
    const float* wk = (const float*)d_in[3];
    const float* wv = (const float*)d_in[4];
    const float* wo = (const float*)d_in[5];
    float* out = (float*)d_out;

    float *q, *k, *v, *o;
    cudaGetSymbolAddress((void**)&q, g_q);
    cudaGetSymbolAddress((void**)&k, g_k);
    cudaGetSymbolAddress((void**)&v, g_v);
    cudaGetSymbolAddress((void**)&o, g_o);

    // Projections
    sgemm_kernel<<<dim3(E_ / 128, ROWS_ / 128), 256>>>(ROWS_, H_ * D_,  E_, x, wq, q);
    sgemm_kernel<<<dim3((KVH_ * D_) / 128, ROWS_ / 128), 256>>>(ROWS_, KVH_ * D_, E_, x, wk, k);
    sgemm_kernel<<<dim3((KVH_ * D_) / 128, ROWS_ / 128), 256>>>(ROWS_, KVH_ * D_, E_, x, wv, v);

    // RoPE on q and k
    {
        int total_q = ROWS_ * H_ * 64;
        int total_k = ROWS_ * KVH_ * 64;
        rope_kernel<<<(total_q + 255) / 256, 256>>>(q, H_, total_q);
        rope_kernel<<<(total_k + 255) / 256, 256>>>(k, KVH_, total_k);
    }

    // Flash attention
    {
        int smem_bytes = FLASH_SMEM_FLOATS * (int)sizeof(float);
        cudaFuncSetAttribute(flash_attn_kernel,
                             cudaFuncAttributeMaxDynamicSharedMemorySize, smem_bytes);
        flash_attn_kernel<<<dim3(T_ / 64, H_, B_), 256, smem_bytes>>>(q, k, v, o);
    }

    // Output projection
    sgemm_kernel<<<dim3(E_ / 128, ROWS_ / 128), 256>>>(ROWS_, E_, H_ * D_, o, wo, out);
}

// round 3
// speedup vs baseline: 1.2404x; 1.2404x over previous
#include <cuda_runtime.h>
#include <cuda_bf16.h>
#include <math.h>
#include <cstdint>

// Problem constants
#define B_  2
#define T_  2048
#define E_  2048
#define H_  16
#define KVH_ 8
#define D_  128
#define ROWS_ (B_ * T_)            // 4096

// ---------------- scratch (device globals; no allocs allowed) ----------------
__device__ float g_q[(size_t)ROWS_ * H_ * D_];
__device__ float g_k[(size_t)ROWS_ * KVH_ * D_];
__device__ float g_v[(size_t)ROWS_ * KVH_ * D_];
__device__ float g_o[(size_t)ROWS_ * H_ * D_];
__device__ float g_wqt[(size_t)E_ * H_ * D_];      // wq^T  [HD, E]
__device__ float g_wkt[(size_t)E_ * KVH_ * D_];    // wk^T  [KVHD, E]
__device__ float g_wvt[(size_t)E_ * KVH_ * D_];
__device__ float g_wot[(size_t)E_ * H_ * D_];      // wo^T  [E, HD]

// ====================== helpers ======================
__device__ __forceinline__ uint32_t smem_u32(const void* p) {
    uint32_t a;
    asm("{ .reg .u64 t; cvta.to.shared.u64 t, %1; cvt.u32.u64 %0, t; }" : "=r"(a) : "l"(p));
    return a;
}
#define CP_ASYNC16(dst, src) \
    asm volatile("cp.async.cg.shared.global [%0], [%1], 16;" :: "r"(dst), "l"(src))
#define CP_COMMIT() asm volatile("cp.async.commit_group;" ::: "memory")
#define CP_WAIT(n)  asm volatile("cp.async.wait_group %0;" :: "n"(n) : "memory")

__device__ __forceinline__ uint32_t f2tf32(float x) {
    uint32_t u;
    asm("cvt.rna.tf32.f32 %0, %1;" : "=r"(u) : "f"(x));
    return u;
}
__device__ __forceinline__ void mma_tf32(float (&c)[4], const uint32_t (&a)[4],
                                         const uint32_t (&b)[2]) {
    asm volatile(
        "mma.sync.aligned.m16n8k8.row.col.f32.tf32.tf32.f32 "
        "{%0,%1,%2,%3}, {%4,%5,%6,%7}, {%8,%9}, {%0,%1,%2,%3};"
        : "+f"(c[0]), "+f"(c[1]), "+f"(c[2]), "+f"(c[3])
        : "r"(a[0]), "r"(a[1]), "r"(a[2]), "r"(a[3]), "r"(b[0]), "r"(b[1]));
}

// ====================== weight transpose: Wt[N,K] = W[K,N] ======================
__global__ void transpose_kernel(const float* __restrict__ W, float* __restrict__ Wt,
                                 int K, int N)
{
    __shared__ float tile[32][33];
    int bx = blockIdx.x * 32;  // n
    int by = blockIdx.y * 32;  // k
    int tx = threadIdx.x, ty = threadIdx.y;
#pragma unroll
    for (int j = 0; j < 32; j += 8)
        tile[ty + j][tx] = W[(size_t)(by + ty + j) * N + bx + tx];
    __syncthreads();
#pragma unroll
    for (int j = 0; j < 32; j += 8)
        Wt[(size_t)(bx + ty + j) * K + by + tx] = tile[tx][ty + j];
}

// ====================== tf32 mma.sync GEMM ======================
// C[M,N] = A[M,K] @ Bt[N,K]^T.  CTA tile 128x128, BK=16, 4-stage cp.async.
// 256 threads = 8 warps; warp tile 64x32 (4x4 of m16n8k8).
#define GBM 128
#define GBN 128
#define GBK 16
#define GSTRIDE 20                         // floats per smem row (BK + 4 pad)
#define GSTAGE_FLOATS (2 * GBM * GSTRIDE)  // A block + B block
#define GSTAGES 4
#define GSMEM_BYTES (GSTAGES * GSTAGE_FLOATS * 4)   // 81920

__global__ void __launch_bounds__(256, 1) tc_gemm_kernel(
    int M, int N, int K,
    const float* __restrict__ A, const float* __restrict__ Bt,
    float* __restrict__ C)
{
    extern __shared__ float smf[];
    const uint32_t smem_base = smem_u32(smf);
    const int tid = threadIdx.x;
    const int wid = tid >> 5, lid = tid & 31;
    const int g = lid >> 2, tig = lid & 3;

    const int m0 = blockIdx.y * GBM;
    const int n0 = blockIdx.x * GBN;
    const float* Ab = A  + (size_t)m0 * K;
    const float* Bb = Bt + (size_t)n0 * K;
    const int nchunks = K / GBK;

    // warp tile: 2 (m) x 4 (n) arrangement -> 64x32 each
    const int wm0 = (wid >> 2) * 64;
    const int wn0 = (wid & 3) * 32;

    float acc[16][4];
#pragma unroll
    for (int i = 0; i < 16; i++)
#pragma unroll
        for (int jj = 0; jj < 4; jj++) acc[i][jj] = 0.f;

    auto load_chunk = [&](int j) {
        const int stage = j & (GSTAGES - 1);
        const uint32_t abase = smem_base + stage * GSTAGE_FLOATS * 4;
        const uint32_t bbase = abase + GBM * GSTRIDE * 4;
        const float* ag = Ab + j * GBK;
        const float* bg = Bb + j * GBK;
#pragma unroll
        for (int i = 0; i < 2; i++) {
            int f = i * 256 + tid;            // 0..511 (128 rows x 4 x 16B)
            int row = f >> 2, c = f & 3;      // c in 16B units
            uint32_t soff = (uint32_t)(row * GSTRIDE + c * 4) * 4;
            CP_ASYNC16(abase + soff, ag + (size_t)row * K + c * 4);
            CP_ASYNC16(bbase + soff, bg + (size_t)row * K + c * 4);
        }
    };

#pragma unroll
    for (int j = 0; j < GSTAGES - 1; j++) { load_chunk(j); CP_COMMIT(); }

    for (int j = 0; j < nchunks; j++) {
        CP_WAIT(GSTAGES - 2);            // chunk j resident
        __syncthreads();                 // also: all warps done with stage (j-1)%4
        int pf = j + GSTAGES - 1;
        if (pf < nchunks) load_chunk(pf);
        CP_COMMIT();

        const int stage = j & (GSTAGES - 1);
        const float* as = smf + stage * GSTAGE_FLOATS;
        const float* bs = as + GBM * GSTRIDE;

#pragma unroll
        for (int ks = 0; ks < 2; ks++) {
            const int k0 = ks * 8;
            uint32_t afr[4][4], bfr[4][2];
#pragma unroll
            for (int mt = 0; mt < 4; mt++) {
                const float* ap = as + (wm0 + mt * 16 + g) * GSTRIDE + k0 + tig;
                afr[mt][0] = f2tf32(ap[0]);
                afr[mt][1] = f2tf32(ap[8 * GSTRIDE]);
                afr[mt][2] = f2tf32(ap[4]);
                afr[mt][3] = f2tf32(ap[8 * GSTRIDE + 4]);
            }
#pragma unroll
            for (int nt = 0; nt < 4; nt++) {
                const float* bp = bs + (wn0 + nt * 8 + g) * GSTRIDE + k0 + tig;
                bfr[nt][0] = f2tf32(bp[0]);
                bfr[nt][1] = f2tf32(bp[4]);
            }
#pragma unroll
            for (int mt = 0; mt < 4; mt++)
#pragma unroll
                for (int nt = 0; nt < 4; nt++)
                    mma_tf32(acc[mt * 4 + nt], afr[mt], bfr[nt]);
        }
        __syncthreads();
    }

    // epilogue: c0:(g, 2tig) c1:(g, 2tig+1) c2:(g+8, 2tig) c3:(g+8, 2tig+1)
#pragma unroll
    for (int mt = 0; mt < 4; mt++) {
#pragma unroll
        for (int nt = 0; nt < 4; nt++) {
            int row = m0 + wm0 + mt * 16 + g;
            int col = n0 + wn0 + nt * 8 + tig * 2;
            float2 lo = { acc[mt * 4 + nt][0], acc[mt * 4 + nt][1] };
            float2 hi = { acc[mt * 4 + nt][2], acc[mt * 4 + nt][3] };
            *(float2*)(C + (size_t)row * N + col) = lo;
            *(float2*)(C + (size_t)(row + 8) * N + col) = hi;
        }
    }
}

// ---------------- RoPE (in place), matches jax fp32 reference ----------------
__global__ void rope_kernel(float* __restrict__ X, int nh, int total)
{
    int idx = blockIdx.x * blockDim.x + threadIdx.x;
    if (idx >= total) return;
    int j = idx & 63;
    int rest = idx >> 6;
    int hh = rest % nh;
    int row = rest / nh;
    int t = row & (T_ - 1);

    float inv = 1.0f / powf(10000.0f, (float)j * (1.0f / 64.0f));
    float ang = (float)t * inv;
    float s, c;
    sincosf(ang, &s, &c);

    float* p = X + (size_t)row * (nh * D_) + hh * D_ + 2 * j;
    float x0 = p[0], x1 = p[1];
    p[0] = x0 * c - x1 * s;
    p[1] = x0 * s + x1 * c;
}

// ---------------- Flash attention (causal, GQA), fp32 -----------------------
#define QKV_PAD 132
#define FLASH_SMEM_FLOATS (3 * 64 * QKV_PAD + 64 * 64 + 3 * 64)

__global__ void __launch_bounds__(256, 1) flash_attn_kernel(
    const float* __restrict__ Q, const float* __restrict__ Kg,
    const float* __restrict__ Vg, float* __restrict__ O)
{
    extern __shared__ float sm[];
    float* Qs = sm;
    float* Ks = Qs + 64 * QKV_PAD;
    float* Vs = Ks + 64 * QKV_PAD;
    float* S  = Vs + 64 * QKV_PAD;
    float* mrow = S + 64 * 64;
    float* lrow = mrow + 64;
    float* arow = lrow + 64;

    const int tid = threadIdx.x;
    const int qt = blockIdx.x, h = blockIdx.y, b = blockIdx.z;
    const int kvh = h >> 1;
    const int q0 = qt * 64;

    {
        int r = tid >> 2, c0 = (tid & 3) * 8;
        const float4* src = (const float4*)(Q + (size_t)(b * T_ + q0 + r) * (H_ * D_) + h * D_) + c0;
        float4* dst = (float4*)(Qs + r * QKV_PAD) + c0;
#pragma unroll
        for (int i = 0; i < 8; i++) dst[i] = src[i];
    }
    if (tid < 64) { mrow[tid] = -INFINITY; lrow[tid] = 0.f; }

    float acc[32];
#pragma unroll
    for (int i = 0; i < 32; i++) acc[i] = 0.f;
    const int r  = tid >> 2;
    const int dh = (tid & 3) * 32;
    const float scale = 0.08838834764831845f;

    for (int kt = 0; kt <= qt; kt++) {
        __syncthreads();
        {
            int rr = tid >> 2, c0 = (tid & 3) * 8;
            size_t gbase = (size_t)(b * T_ + kt * 64 + rr) * (KVH_ * D_) + kvh * D_;
            const float4* ksrc = (const float4*)(Kg + gbase) + c0;
            const float4* vsrc = (const float4*)(Vg + gbase) + c0;
            float4* kd = (float4*)(Ks + rr * QKV_PAD) + c0;
            float4* vd = (float4*)(Vs + rr * QKV_PAD) + c0;
#pragma unroll
            for (int i = 0; i < 8; i++) { kd[i] = ksrc[i]; vd[i] = vsrc[i]; }
        }
        __syncthreads();

        {
            const int tr = tid >> 4;
            const int tc = tid & 15;
            float s4[4][4];
#pragma unroll
            for (int i = 0; i < 4; i++)
#pragma unroll
                for (int jj = 0; jj < 4; jj++) s4[i][jj] = 0.f;

            const float* qb = Qs + (tr * 4) * QKV_PAD;
            for (int d = 0; d < 128; d++) {
                float kvv[4];
#pragma unroll
                for (int jj = 0; jj < 4; jj++)
                    kvv[jj] = Ks[(tc + 16 * jj) * QKV_PAD + d];
#pragma unroll
                for (int i = 0; i < 4; i++) {
                    float qv = qb[i * QKV_PAD + d];
#pragma unroll
                    for (int jj = 0; jj < 4; jj++)
                        s4[i][jj] = fmaf(qv, kvv[jj], s4[i][jj]);
                }
            }
            const bool diag = (kt == qt);
#pragma unroll
            for (int i = 0; i < 4; i++) {
                int gi = tr * 4 + i;
#pragma unroll
                for (int jj = 0; jj < 4; jj++) {
                    int gj = tc + 16 * jj;
                    float v = s4[i][jj] * scale;
                    if (diag && gj > gi) v = -1e30f;
                    S[gi * 64 + gj] = v;
                }
            }
        }
        __syncthreads();

        if (tid < 64) {
            float m_old = mrow[tid];
            float mx = m_old;
            float* srow = S + tid * 64;
#pragma unroll 8
            for (int j = 0; j < 64; j++) mx = fmaxf(mx, srow[j]);
            float sum = 0.f;
#pragma unroll 8
            for (int j = 0; j < 64; j++) {
                float p = __expf(srow[j] - mx);
                srow[j] = p;
                sum += p;
            }
            float al = __expf(m_old - mx);
            lrow[tid] = lrow[tid] * al + sum;
            mrow[tid] = mx;
            arow[tid] = al;
        }
        __syncthreads();

        {
            float al = arow[r];
#pragma unroll
            for (int i = 0; i < 32; i++) acc[i] *= al;
            const float* srow = S + r * 64;
#pragma unroll 4
            for (int j = 0; j < 64; j++) {
                float p = srow[j];
                const float4* vr = (const float4*)(Vs + j * QKV_PAD + dh);
#pragma unroll
                for (int d4 = 0; d4 < 8; d4++) {
                    float4 vv = vr[d4];
                    acc[d4 * 4 + 0] = fmaf(p, vv.x, acc[d4 * 4 + 0]);
                    acc[d4 * 4 + 1] = fmaf(p, vv.y, acc[d4 * 4 + 1]);
                    acc[d4 * 4 + 2] = fmaf(p, vv.z, acc[d4 * 4 + 2]);
                    acc[d4 * 4 + 3] = fmaf(p, vv.w, acc[d4 * 4 + 3]);
                }
            }
        }
    }

    {
        float inv_l = 1.f / lrow[r];
        float* dst = O + (size_t)(b * T_ + q0 + r) * (H_ * D_) + h * D_ + dh;
#pragma unroll
        for (int d4 = 0; d4 < 8; d4++) {
            float4 o4 = { acc[d4 * 4 + 0] * inv_l, acc[d4 * 4 + 1] * inv_l,
                          acc[d4 * 4 + 2] * inv_l, acc[d4 * 4 + 3] * inv_l };
            ((float4*)dst)[d4] = o4;
        }
    }
}

// -------------------------------- launch -------------------------------------
extern "C" void kernel_launch(void* const* d_in, const int* in_sizes, int n_in,
                              void* d_out, int out_size)
{
    const float* x  = (const float*)d_in[0];
    const float* wq = (const float*)d_in[2];
    const float* wk = (const float*)d_in[3];
    const float* wv = (const float*)d_in[4];
    const float* wo = (const float*)d_in[5];
    float* out = (float*)d_out;

    float *q, *k, *v, *o, *wqt, *wkt, *wvt, *wot;
    cudaGetSymbolAddress((void**)&q, g_q);
    cudaGetSymbolAddress((void**)&k, g_k);
    cudaGetSymbolAddress((void**)&v, g_v);
    cudaGetSymbolAddress((void**)&o, g_o);
    cudaGetSymbolAddress((void**)&wqt, g_wqt);
    cudaGetSymbolAddress((void**)&wkt, g_wkt);
    cudaGetSymbolAddress((void**)&wvt, g_wvt);
    cudaGetSymbolAddress((void**)&wot, g_wot);

    dim3 tb(32, 8);
    transpose_kernel<<<dim3((H_ * D_) / 32, E_ / 32), tb>>>(wq, wqt, E_, H_ * D_);
    transpose_kernel<<<dim3((KVH_ * D_) / 32, E_ / 32), tb>>>(wk, wkt, E_, KVH_ * D_);
    transpose_kernel<<<dim3((KVH_ * D_) / 32, E_ / 32), tb>>>(wv, wvt, E_, KVH_ * D_);
    transpose_kernel<<<dim3(E_ / 32, (H_ * D_) / 32), tb>>>(wo, wot, H_ * D_, E_);

    cudaFuncSetAttribute(tc_gemm_kernel,
                         cudaFuncAttributeMaxDynamicSharedMemorySize, GSMEM_BYTES);

    // Projections: C = x @ W  via  A[M,K] * Wt[N,K]^T
    tc_gemm_kernel<<<dim3((H_ * D_) / 128, ROWS_ / 128), 256, GSMEM_BYTES>>>(
        ROWS_, H_ * D_, E_, x, wqt, q);
    tc_gemm_kernel<<<dim3((KVH_ * D_) / 128, ROWS_ / 128), 256, GSMEM_BYTES>>>(
        ROWS_, KVH_ * D_, E_, x, wkt, k);
    tc_gemm_kernel<<<dim3((KVH_ * D_) / 128, ROWS_ / 128), 256, GSMEM_BYTES>>>(
        ROWS_, KVH_ * D_, E_, x, wvt, v);

    // RoPE on q and k
    {
        int total_q = ROWS_ * H_ * 64;
        int total_k = ROWS_ * KVH_ * 64;
        rope_kernel<<<(total_q + 255) / 256, 256>>>(q, H_, total_q);
        rope_kernel<<<(total_k + 255) / 256, 256>>>(k, KVH_, total_k);
    }

    // Flash attention (fp32, unchanged this round)
    {
        int smem_bytes = FLASH_SMEM_FLOATS * (int)sizeof(float);
        cudaFuncSetAttribute(flash_attn_kernel,
                             cudaFuncAttributeMaxDynamicSharedMemorySize, smem_bytes);
        flash_attn_kernel<<<dim3(T_ / 64, H_, B_), 256, smem_bytes>>>(q, k, v, o);
    }

    // Output projection
    tc_gemm_kernel<<<dim3(E_ / 128, ROWS_ / 128), 256, GSMEM_BYTES>>>(
        ROWS_, E_, H_ * D_, o, wot, out);
}

// round 4
// speedup vs baseline: 4.4142x; 3.5586x over previous
#include <cuda_runtime.h>
#include <cuda_bf16.h>
#include <math.h>
#include <cstdint>

// Problem constants
#define B_  2
#define T_  2048
#define E_  2048
#define H_  16
#define KVH_ 8
#define D_  128
#define ROWS_ (B_ * T_)            // 4096

// ---------------- scratch (device globals; no allocs allowed) ----------------
__device__ float g_q[(size_t)ROWS_ * H_ * D_];
__device__ float g_k[(size_t)ROWS_ * KVH_ * D_];
__device__ float g_v[(size_t)ROWS_ * KVH_ * D_];
__device__ float g_o[(size_t)ROWS_ * H_ * D_];
__device__ float g_xr[(size_t)ROWS_ * E_];         // tf32-rounded x
__device__ float g_wqt[(size_t)E_ * H_ * D_];      // wq^T  [HD, E]  (tf32-rounded)
__device__ float g_wkt[(size_t)E_ * KVH_ * D_];
__device__ float g_wvt[(size_t)E_ * KVH_ * D_];
__device__ float g_wot[(size_t)E_ * H_ * D_];

// ====================== helpers ======================
__device__ __forceinline__ uint32_t smem_u32(const void* p) {
    uint32_t a;
    asm("{ .reg .u64 t; cvta.to.shared.u64 t, %1; cvt.u32.u64 %0, t; }" : "=r"(a) : "l"(p));
    return a;
}
#define CP_ASYNC16(dst, src) \
    asm volatile("cp.async.cg.shared.global [%0], [%1], 16;" :: "r"(dst), "l"(src))
#define CP_COMMIT() asm volatile("cp.async.commit_group;" ::: "memory")
#define CP_WAIT(n)  asm volatile("cp.async.wait_group %0;" :: "n"(n) : "memory")

__device__ __forceinline__ uint32_t f2tf32(float x) {
    uint32_t u;
    asm("cvt.rna.tf32.f32 %0, %1;" : "=r"(u) : "f"(x));
    return u;
}
__device__ __forceinline__ float tf32r(float x) {
    return __uint_as_float(f2tf32(x));
}
__device__ __forceinline__ void mma_tf32(float (&c)[4], const uint32_t (&a)[4],
                                         const uint32_t (&b)[2]) {
    asm volatile(
        "mma.sync.aligned.m16n8k8.row.col.f32.tf32.tf32.f32 "
        "{%0,%1,%2,%3}, {%4,%5,%6,%7}, {%8,%9}, {%0,%1,%2,%3};"
        : "+f"(c[0]), "+f"(c[1]), "+f"(c[2]), "+f"(c[3])
        : "r"(a[0]), "r"(a[1]), "r"(a[2]), "r"(a[3]), "r"(b[0]), "r"(b[1]));
}

// ============== round x to tf32 (float4 at a time) ==============
__global__ void round_tf32_kernel(const float* __restrict__ in, float* __restrict__ out,
                                  int n4)
{
    int i = blockIdx.x * blockDim.x + threadIdx.x;
    if (i >= n4) return;
    float4 t = ((const float4*)in)[i];
    t.x = tf32r(t.x); t.y = tf32r(t.y); t.z = tf32r(t.z); t.w = tf32r(t.w);
    ((float4*)out)[i] = t;
}

// ====================== weight transpose: Wt[N,K] = tf32(W[K,N]) ======================
__global__ void transpose_kernel(const float* __restrict__ W, float* __restrict__ Wt,
                                 int K, int N)
{
    __shared__ float tile[32][33];
    int bx = blockIdx.x * 32;  // n
    int by = blockIdx.y * 32;  // k
    int tx = threadIdx.x, ty = threadIdx.y;
#pragma unroll
    for (int j = 0; j < 32; j += 8)
        tile[ty + j][tx] = W[(size_t)(by + ty + j) * N + bx + tx];
    __syncthreads();
#pragma unroll
    for (int j = 0; j < 32; j += 8)
        Wt[(size_t)(bx + ty + j) * K + by + tx] = tf32r(tile[tx][ty + j]);
}

// ====================== tf32 mma.sync GEMM ======================
// C[M,N] = A[M,K] @ Bt[N,K]^T.  CTA tile 128x128, BK=16, 4-stage cp.async.
// 256 threads = 8 warps; warp tile 64x32 (4x4 of m16n8k8). Inputs pre-rounded to tf32.
#define GBM 128
#define GBN 128
#define GBK 16
#define GSTRIDE 20
#define GSTAGE_FLOATS (2 * GBM * GSTRIDE)
#define GSTAGES 4
#define GSMEM_BYTES (GSTAGES * GSTAGE_FLOATS * 4)   // 81920

__global__ void __launch_bounds__(256, 1) tc_gemm_kernel(
    int M, int N, int K,
    const float* __restrict__ A, const float* __restrict__ Bt,
    float* __restrict__ C)
{
    extern __shared__ float smf[];
    const uint32_t smem_base = smem_u32(smf);
    const int tid = threadIdx.x;
    const int wid = tid >> 5, lid = tid & 31;
    const int g = lid >> 2, tig = lid & 3;

    const int m0 = blockIdx.y * GBM;
    const int n0 = blockIdx.x * GBN;
    const float* Ab = A  + (size_t)m0 * K;
    const float* Bb = Bt + (size_t)n0 * K;
    const int nchunks = K / GBK;

    const int wm0 = (wid >> 2) * 64;
    const int wn0 = (wid & 3) * 32;

    float acc[16][4];
#pragma unroll
    for (int i = 0; i < 16; i++)
#pragma unroll
        for (int jj = 0; jj < 4; jj++) acc[i][jj] = 0.f;

    auto load_chunk = [&](int j) {
        const int stage = j & (GSTAGES - 1);
        const uint32_t abase = smem_base + stage * GSTAGE_FLOATS * 4;
        const uint32_t bbase = abase + GBM * GSTRIDE * 4;
        const float* ag = Ab + j * GBK;
        const float* bg = Bb + j * GBK;
#pragma unroll
        for (int i = 0; i < 2; i++) {
            int f = i * 256 + tid;
            int row = f >> 2, c = f & 3;
            uint32_t soff = (uint32_t)(row * GSTRIDE + c * 4) * 4;
            CP_ASYNC16(abase + soff, ag + (size_t)row * K + c * 4);
            CP_ASYNC16(bbase + soff, bg + (size_t)row * K + c * 4);
        }
    };

#pragma unroll
    for (int j = 0; j < GSTAGES - 1; j++) { load_chunk(j); CP_COMMIT(); }

    for (int j = 0; j < nchunks; j++) {
        CP_WAIT(GSTAGES - 2);
        __syncthreads();
        int pf = j + GSTAGES - 1;
        if (pf < nchunks) load_chunk(pf);
        CP_COMMIT();

        const int stage = j & (GSTAGES - 1);
        const float* as = smf + stage * GSTAGE_FLOATS;
        const float* bs = as + GBM * GSTRIDE;

#pragma unroll
        for (int ks = 0; ks < 2; ks++) {
            const int k0 = ks * 8;
            uint32_t afr[4][4], bfr[4][2];
#pragma unroll
            for (int mt = 0; mt < 4; mt++) {
                const uint32_t* ap = (const uint32_t*)(as + (wm0 + mt * 16 + g) * GSTRIDE + k0 + tig);
                afr[mt][0] = ap[0];
                afr[mt][1] = ap[8 * GSTRIDE];
                afr[mt][2] = ap[4];
                afr[mt][3] = ap[8 * GSTRIDE + 4];
            }
#pragma unroll
            for (int nt = 0; nt < 4; nt++) {
                const uint32_t* bp = (const uint32_t*)(bs + (wn0 + nt * 8 + g) * GSTRIDE + k0 + tig);
                bfr[nt][0] = bp[0];
                bfr[nt][1] = bp[4];
            }
#pragma unroll
            for (int mt = 0; mt < 4; mt++)
#pragma unroll
                for (int nt = 0; nt < 4; nt++)
                    mma_tf32(acc[mt * 4 + nt], afr[mt], bfr[nt]);
        }
        __syncthreads();
    }

#pragma unroll
    for (int mt = 0; mt < 4; mt++) {
#pragma unroll
        for (int nt = 0; nt < 4; nt++) {
            int row = m0 + wm0 + mt * 16 + g;
            int col = n0 + wn0 + nt * 8 + tig * 2;
            float2 lo = { acc[mt * 4 + nt][0], acc[mt * 4 + nt][1] };
            float2 hi = { acc[mt * 4 + nt][2], acc[mt * 4 + nt][3] };
            *(float2*)(C + (size_t)row * N + col) = lo;
            *(float2*)(C + (size_t)(row + 8) * N + col) = hi;
        }
    }
}

// ---------------- RoPE (in place), fp32 rotate then tf32-round --------------
__global__ void rope_kernel(float* __restrict__ X, int nh, int total)
{
    int idx = blockIdx.x * blockDim.x + threadIdx.x;
    if (idx >= total) return;
    int j = idx & 63;
    int rest = idx >> 6;
    int hh = rest % nh;
    int row = rest / nh;
    int t = row & (T_ - 1);

    float inv = 1.0f / powf(10000.0f, (float)j * (1.0f / 64.0f));
    float ang = (float)t * inv;
    float s, c;
    sincosf(ang, &s, &c);

    float* p = X + (size_t)row * (nh * D_) + hh * D_ + 2 * j;
    float x0 = p[0], x1 = p[1];
    p[0] = tf32r(x0 * c - x1 * s);
    p[1] = tf32r(x0 * s + x1 * c);
}

// ---------------- Flash attention (causal, GQA), tf32 mma -----------------
// grid (T/64, H, B), 256 threads = 8 warps.
// QK^T: warps 4(m)x2(n), warp tile 16x32. PV: warps 4(m)x2(n), warp tile 16x64.
#define FQ_STRIDE 132
#define FS_STRIDE 68
#define FV_STRIDE 68
#define FLASH_SMEM_FLOATS (2 * 64 * FQ_STRIDE + 128 * FV_STRIDE + 64 * FS_STRIDE + 3 * 64)

__global__ void __launch_bounds__(256, 1) flash_attn_kernel(
    const float* __restrict__ Q, const float* __restrict__ Kg,
    const float* __restrict__ Vg, float* __restrict__ O)
{
    extern __shared__ float sm[];
    float* Qs = sm;                         // 64 x 132
    float* Ks = Qs + 64 * FQ_STRIDE;        // 64 x 132
    float* Vt = Ks + 64 * FQ_STRIDE;        // 128 x 68 (V transposed: [d][seq])
    float* S  = Vt + 128 * FV_STRIDE;       // 64 x 68
    float* mrow = S + 64 * FS_STRIDE;
    float* lrow = mrow + 64;
    float* arow = lrow + 64;

    const int tid = threadIdx.x;
    const int wid = tid >> 5, lid = tid & 31;
    const int g = lid >> 2, tig = lid & 3;
    const int qt = blockIdx.x, h = blockIdx.y, b = blockIdx.z;
    const int kvh = h >> 1;
    const int q0 = qt * 64;

    const int wr  = (wid >> 1) * 16;   // warp row base (both QK and PV)
    const int wcq = (wid & 1) * 32;    // QK col base
    const int wcv = (wid & 1) * 64;    // PV d base

    // load Q tile (pre-rounded tf32 bits)
    {
        int r = tid >> 2, c0 = (tid & 3) * 8;
        const float4* src = (const float4*)(Q + (size_t)(b * T_ + q0 + r) * (H_ * D_) + h * D_) + c0;
        float4* dst = (float4*)(Qs + r * FQ_STRIDE) + c0;
#pragma unroll
        for (int i = 0; i < 8; i++) dst[i] = src[i];
    }
    if (tid < 64) { mrow[tid] = -INFINITY; lrow[tid] = 0.f; }
    __syncthreads();

    float oacc[8][4];
#pragma unroll
    for (int i = 0; i < 8; i++)
#pragma unroll
        for (int jj = 0; jj < 4; jj++) oacc[i][jj] = 0.f;

    const float scale = 0.08838834764831845f; // 1/sqrt(128)

    for (int kt = 0; kt <= qt; kt++) {
        __syncthreads();  // prev-iter PV done -> Ks/Vt reusable
        // load K tile; load V transposed (+tf32 round)
        {
            int rr = tid >> 2, c0 = (tid & 3) * 8;
            size_t gbase = (size_t)(b * T_ + kt * 64 + rr) * (KVH_ * D_) + kvh * D_;
            const float4* ksrc = (const float4*)(Kg + gbase) + c0;
            const float4* vsrc = (const float4*)(Vg + gbase) + c0;
            float4* kd = (float4*)(Ks + rr * FQ_STRIDE) + c0;
#pragma unroll
            for (int i = 0; i < 8; i++) {
                kd[i] = ksrc[i];
                float4 v4 = vsrc[i];
                int d0 = (c0 + i) * 4;
                Vt[(d0 + 0) * FV_STRIDE + rr] = tf32r(v4.x);
                Vt[(d0 + 1) * FV_STRIDE + rr] = tf32r(v4.y);
                Vt[(d0 + 2) * FV_STRIDE + rr] = tf32r(v4.z);
                Vt[(d0 + 3) * FV_STRIDE + rr] = tf32r(v4.w);
            }
        }
        __syncthreads();

        // ---- QK^T via mma: warp tile 16x32 (1 mt x 4 nt), K=128 in 16 steps
        float sacc[4][4];
#pragma unroll
        for (int nt = 0; nt < 4; nt++)
#pragma unroll
            for (int jj = 0; jj < 4; jj++) sacc[nt][jj] = 0.f;

#pragma unroll
        for (int ks = 0; ks < 16; ks++) {
            const int k0 = ks * 8;
            uint32_t a[4];
            const uint32_t* ap = (const uint32_t*)(Qs + (wr + g) * FQ_STRIDE + k0 + tig);
            a[0] = ap[0];
            a[1] = ap[8 * FQ_STRIDE];
            a[2] = ap[4];
            a[3] = ap[8 * FQ_STRIDE + 4];
#pragma unroll
            for (int nt = 0; nt < 4; nt++) {
                uint32_t bb[2];
                const uint32_t* bp = (const uint32_t*)(Ks + (wcq + nt * 8 + g) * FQ_STRIDE + k0 + tig);
                bb[0] = bp[0];
                bb[1] = bp[4];
                mma_tf32(sacc[nt], a, bb);
            }
        }
        // mask + scale + store S
        {
            const bool diag = (kt == qt);
            const int gi0 = wr + g, gi1 = wr + g + 8;
#pragma unroll
            for (int nt = 0; nt < 4; nt++) {
                int gj = wcq + nt * 8 + 2 * tig;
                float s0 = sacc[nt][0] * scale;
                float s1 = sacc[nt][1] * scale;
                float s2 = sacc[nt][2] * scale;
                float s3 = sacc[nt][3] * scale;
                if (diag) {
                    if (gj     > gi0) s0 = -1e30f;
                    if (gj + 1 > gi0) s1 = -1e30f;
                    if (gj     > gi1) s2 = -1e30f;
                    if (gj + 1 > gi1) s3 = -1e30f;
                }
                *(float2*)(S + gi0 * FS_STRIDE + gj) = make_float2(s0, s1);
                *(float2*)(S + gi1 * FS_STRIDE + gj) = make_float2(s2, s3);
            }
        }
        __syncthreads();

        // ---- online softmax: 4 threads per row, shfl combine (lanes 4-aligned)
        {
            int row = tid >> 2, qq = tid & 3;
            float* srow = S + row * FS_STRIDE + qq * 16;
            float mx = -INFINITY;
#pragma unroll
            for (int j = 0; j < 16; j++) mx = fmaxf(mx, srow[j]);
            mx = fmaxf(mx, __shfl_xor_sync(0xFFFFFFFF, mx, 1));
            mx = fmaxf(mx, __shfl_xor_sync(0xFFFFFFFF, mx, 2));
            float m_old = mrow[row];
            mx = fmaxf(mx, m_old);
            float sum = 0.f;
#pragma unroll
            for (int j = 0; j < 16; j++) {
                float p = tf32r(__expf(srow[j] - mx));
                srow[j] = p;
                sum += p;
            }
            sum += __shfl_xor_sync(0xFFFFFFFF, sum, 1);
            sum += __shfl_xor_sync(0xFFFFFFFF, sum, 2);
            if (qq == 0) {
                float al = __expf(m_old - mx);
                lrow[row] = lrow[row] * al + sum;
                mrow[row] = mx;
                arow[row] = al;
            }
        }
        __syncthreads();

        // ---- PV via mma: warp tile 16x64 (8 nt), K=64 in 8 steps
        {
            float al0 = arow[wr + g], al1 = arow[wr + g + 8];
#pragma unroll
            for (int nt = 0; nt < 8; nt++) {
                oacc[nt][0] *= al0; oacc[nt][1] *= al0;
                oacc[nt][2] *= al1; oacc[nt][3] *= al1;
            }
#pragma unroll
            for (int ks = 0; ks < 8; ks++) {
                const int k0 = ks * 8;
                uint32_t a[4];
                const uint32_t* ap = (const uint32_t*)(S + (wr + g) * FS_STRIDE + k0 + tig);
                a[0] = ap[0];
                a[1] = ap[8 * FS_STRIDE];
                a[2] = ap[4];
                a[3] = ap[8 * FS_STRIDE + 4];
#pragma unroll
                for (int nt = 0; nt < 8; nt++) {
                    uint32_t bb[2];
                    const uint32_t* bp = (const uint32_t*)(Vt + (wcv + nt * 8 + g) * FV_STRIDE + k0 + tig);
                    bb[0] = bp[0];
                    bb[1] = bp[4];
                    mma_tf32(oacc[nt], a, bb);
                }
            }
        }
    }

    // epilogue: normalize, tf32-round (feeds out-proj), store
    {
        float il0 = 1.f / lrow[wr + g];
        float il1 = 1.f / lrow[wr + g + 8];
        float* O0 = O + (size_t)(b * T_ + q0 + wr + g) * (H_ * D_) + h * D_;
        float* O1 = O + (size_t)(b * T_ + q0 + wr + g + 8) * (H_ * D_) + h * D_;
#pragma unroll
        for (int nt = 0; nt < 8; nt++) {
            int col = wcv + nt * 8 + 2 * tig;
            *(float2*)(O0 + col) = make_float2(tf32r(oacc[nt][0] * il0), tf32r(oacc[nt][1] * il0));
            *(float2*)(O1 + col) = make_float2(tf32r(oacc[nt][2] * il1), tf32r(oacc[nt][3] * il1));
        }
    }
}

// -------------------------------- launch -------------------------------------
extern "C" void kernel_launch(void* const* d_in, const int* in_sizes, int n_in,
                              void* d_out, int out_size)
{
    const float* x  = (const float*)d_in[0];
    const float* wq = (const float*)d_in[2];
    const float* wk = (const float*)d_in[3];
    const float* wv = (const float*)d_in[4];
    const float* wo = (const float*)d_in[5];
    float* out = (float*)d_out;

    float *q, *k, *v, *o, *xr, *wqt, *wkt, *wvt, *wot;
    cudaGetSymbolAddress((void**)&q, g_q);
    cudaGetSymbolAddress((void**)&k, g_k);
    cudaGetSymbolAddress((void**)&v, g_v);
    cudaGetSymbolAddress((void**)&o, g_o);
    cudaGetSymbolAddress((void**)&xr, g_xr);
    cudaGetSymbolAddress((void**)&wqt, g_wqt);
    cudaGetSymbolAddress((void**)&wkt, g_wkt);
    cudaGetSymbolAddress((void**)&wvt, g_wvt);
    cudaGetSymbolAddress((void**)&wot, g_wot);

    // tf32-round x; transpose+round weights
    round_tf32_kernel<<<(ROWS_ * E_ / 4 + 255) / 256, 256>>>(x, xr, ROWS_ * E_ / 4);
    dim3 tb(32, 8);
    transpose_kernel<<<dim3((H_ * D_) / 32, E_ / 32), tb>>>(wq, wqt, E_, H_ * D_);
    transpose_kernel<<<dim3((KVH_ * D_) / 32, E_ / 32), tb>>>(wk, wkt, E_, KVH_ * D_);
    transpose_kernel<<<dim3((KVH_ * D_) / 32, E_ / 32), tb>>>(wv, wvt, E_, KVH_ * D_);
    transpose_kernel<<<dim3(E_ / 32, (H_ * D_) / 32), tb>>>(wo, wot, H_ * D_, E_);

    cudaFuncSetAttribute(tc_gemm_kernel,
                         cudaFuncAttributeMaxDynamicSharedMemorySize, GSMEM_BYTES);

    tc_gemm_kernel<<<dim3((H_ * D_) / 128, ROWS_ / 128), 256, GSMEM_BYTES>>>(
        ROWS_, H_ * D_, E_, xr, wqt, q);
    tc_gemm_kernel<<<dim3((KVH_ * D_) / 128, ROWS_ / 128), 256, GSMEM_BYTES>>>(
        ROWS_, KVH_ * D_, E_, xr, wkt, k);
    tc_gemm_kernel<<<dim3((KVH_ * D_) / 128, ROWS_ / 128), 256, GSMEM_BYTES>>>(
        ROWS_, KVH_ * D_, E_, xr, wvt, v);

    // RoPE on q and k (rotate fp32, write tf32-rounded)
    {
        int total_q = ROWS_ * H_ * 64;
        int total_k = ROWS_ * KVH_ * 64;
        rope_kernel<<<(total_q + 255) / 256, 256>>>(q, H_, total_q);
        rope_kernel<<<(total_k + 255) / 256, 256>>>(k, KVH_, total_k);
    }

    // Flash attention (tf32 mma)
    {
        int smem_bytes = FLASH_SMEM_FLOATS * (int)sizeof(float);
        cudaFuncSetAttribute(flash_attn_kernel,
                             cudaFuncAttributeMaxDynamicSharedMemorySize, smem_bytes);
        flash_attn_kernel<<<dim3(T_ / 64, H_, B_), 256, smem_bytes>>>(q, k, v, o);
    }

    // Output projection
    tc_gemm_kernel<<<dim3(E_ / 128, ROWS_ / 128), 256, GSMEM_BYTES>>>(
        ROWS_, E_, H_ * D_, o, wot, out);
}

// round 6
// speedup vs baseline: 5.8802x; 1.3321x over previous
#include <cuda_runtime.h>
#include <cuda_bf16.h>
#include <math.h>
#include <cstdint>

// Problem constants
#define B_  2
#define T_  2048
#define E_  2048
#define H_  16
#define KVH_ 8
#define D_  128
#define ROWS_ (B_ * T_)            // 4096
#define QKVN (H_ * D_ + 2 * KVH_ * D_)   // 4096 fused N

// ---------------- scratch (device globals; no allocs allowed) ----------------
__device__ float g_qkv[(size_t)ROWS_ * QKVN];      // fused q|k|v, 64 MB
__device__ float g_o[(size_t)ROWS_ * H_ * D_];     // attn out, 32 MB
__device__ float g_xr[(size_t)ROWS_ * E_];         // tf32-rounded x
__device__ float g_wqkvt[(size_t)QKVN * E_];       // [wq|wk|wv]^T rows, tf32
__device__ float g_wot[(size_t)E_ * H_ * D_];

// ====================== helpers ======================
__device__ __forceinline__ uint32_t smem_u32(const void* p) {
    uint32_t a;
    asm("{ .reg .u64 t; cvta.to.shared.u64 t, %1; cvt.u32.u64 %0, t; }" : "=r"(a) : "l"(p));
    return a;
}
#define CP_ASYNC16(dst, src) \
    asm volatile("cp.async.cg.shared.global [%0], [%1], 16;" :: "r"(dst), "l"(src))
#define CP_COMMIT() asm volatile("cp.async.commit_group;" ::: "memory")
#define CP_WAIT(n)  asm volatile("cp.async.wait_group %0;" :: "n"(n) : "memory")

__device__ __forceinline__ uint32_t f2tf32(float x) {
    uint32_t u;
    asm("cvt.rna.tf32.f32 %0, %1;" : "=r"(u) : "f"(x));
    return u;
}
__device__ __forceinline__ float tf32r(float x) {
    return __uint_as_float(f2tf32(x));
}
__device__ __forceinline__ void mma_tf32(float (&c)[4], const uint32_t (&a)[4],
                                         const uint32_t (&b)[2]) {
    asm volatile(
        "mma.sync.aligned.m16n8k8.row.col.f32.tf32.tf32.f32 "
        "{%0,%1,%2,%3}, {%4,%5,%6,%7}, {%8,%9}, {%0,%1,%2,%3};"
        : "+f"(c[0]), "+f"(c[1]), "+f"(c[2]), "+f"(c[3])
        : "r"(a[0]), "r"(a[1]), "r"(a[2]), "r"(a[3]), "r"(b[0]), "r"(b[1]));
}

// ============== round x to tf32 ==============
__global__ void round_tf32_kernel(const float* __restrict__ in, float* __restrict__ out,
                                  int n4)
{
    int i = blockIdx.x * blockDim.x + threadIdx.x;
    if (i >= n4) return;
    float4 t = ((const float4*)in)[i];
    t.x = tf32r(t.x); t.y = tf32r(t.y); t.z = tf32r(t.z); t.w = tf32r(t.w);
    ((float4*)out)[i] = t;
}

// ============ weight transpose: Wt[N,K] = tf32(W[K,N]) ============
__global__ void transpose_kernel(const float* __restrict__ W, float* __restrict__ Wt,
                                 int K, int N)
{
    __shared__ float tile[32][33];
    int bx = blockIdx.x * 32;  // n
    int by = blockIdx.y * 32;  // k
    int tx = threadIdx.x, ty = threadIdx.y;
#pragma unroll
    for (int j = 0; j < 32; j += 8)
        tile[ty + j][tx] = W[(size_t)(by + ty + j) * N + bx + tx];
    __syncthreads();
#pragma unroll
    for (int j = 0; j < 32; j += 8)
        Wt[(size_t)(bx + ty + j) * K + by + tx] = tf32r(tile[tx][ty + j]);
}

// ====================== tf32 mma.sync GEMM ======================
// C[M,N] = A[M,K] @ Bt[N,K]^T.  CTA tile 128x128, BK=16, 3-stage cp.async,
// 2 CTAs/SM. 256 threads = 8 warps; warp tile 64x32.
#define GBM 128
#define GBN 128
#define GBK 16
#define GSTRIDE 20
#define GSTAGE_FLOATS (2 * GBM * GSTRIDE)
#define GSTAGES 3
#define GSMEM_BYTES (GSTAGES * GSTAGE_FLOATS * 4)   // 61440

__global__ void __launch_bounds__(256, 2) tc_gemm_kernel(
    int M, int N, int K,
    const float* __restrict__ A, const float* __restrict__ Bt,
    float* __restrict__ C)
{
    extern __shared__ float smf[];
    const uint32_t smem_base = smem_u32(smf);
    const int tid = threadIdx.x;
    const int wid = tid >> 5, lid = tid & 31;
    const int g = lid >> 2, tig = lid & 3;

    const int m0 = blockIdx.y * GBM;
    const int n0 = blockIdx.x * GBN;
    const float* Ab = A  + (size_t)m0 * K;
    const float* Bb = Bt + (size_t)n0 * K;
    const int nchunks = K / GBK;

    const int wm0 = (wid >> 2) * 64;
    const int wn0 = (wid & 3) * 32;

    float acc[16][4];
#pragma unroll
    for (int i = 0; i < 16; i++)
#pragma unroll
        for (int jj = 0; jj < 4; jj++) acc[i][jj] = 0.f;

    auto load_chunk = [&](int j) {
        const int stage = j % GSTAGES;
        const uint32_t abase = smem_base + stage * GSTAGE_FLOATS * 4;
        const uint32_t bbase = abase + GBM * GSTRIDE * 4;
        const float* ag = Ab + j * GBK;
        const float* bg = Bb + j * GBK;
#pragma unroll
        for (int i = 0; i < 2; i++) {
            int f = i * 256 + tid;
            int row = f >> 2, c = f & 3;
            uint32_t soff = (uint32_t)(row * GSTRIDE + c * 4) * 4;
            CP_ASYNC16(abase + soff, ag + (size_t)row * K + c * 4);
            CP_ASYNC16(bbase + soff, bg + (size_t)row * K + c * 4);
        }
    };

#pragma unroll
    for (int j = 0; j < GSTAGES - 1; j++) { load_chunk(j); CP_COMMIT(); }

    for (int j = 0; j < nchunks; j++) {
        CP_WAIT(GSTAGES - 2);
        __syncthreads();
        int pf = j + GSTAGES - 1;
        if (pf < nchunks) load_chunk(pf);
        CP_COMMIT();

        const int stage = j % GSTAGES;
        const float* as = smf + stage * GSTAGE_FLOATS;
        const float* bs = as + GBM * GSTRIDE;

#pragma unroll
        for (int ks = 0; ks < 2; ks++) {
            const int k0 = ks * 8;
            uint32_t afr[4][4], bfr[4][2];
#pragma unroll
            for (int mt = 0; mt < 4; mt++) {
                const uint32_t* ap = (const uint32_t*)(as + (wm0 + mt * 16 + g) * GSTRIDE + k0 + tig);
                afr[mt][0] = ap[0];
                afr[mt][1] = ap[8 * GSTRIDE];
                afr[mt][2] = ap[4];
                afr[mt][3] = ap[8 * GSTRIDE + 4];
            }
#pragma unroll
            for (int nt = 0; nt < 4; nt++) {
                const uint32_t* bp = (const uint32_t*)(bs + (wn0 + nt * 8 + g) * GSTRIDE + k0 + tig);
                bfr[nt][0] = bp[0];
                bfr[nt][1] = bp[4];
            }
#pragma unroll
            for (int mt = 0; mt < 4; mt++)
#pragma unroll
                for (int nt = 0; nt < 4; nt++)
                    mma_tf32(acc[mt * 4 + nt], afr[mt], bfr[nt]);
        }
        __syncthreads();
    }

#pragma unroll
    for (int mt = 0; mt < 4; mt++) {
#pragma unroll
        for (int nt = 0; nt < 4; nt++) {
            int row = m0 + wm0 + mt * 16 + g;
            int col = n0 + wn0 + nt * 8 + tig * 2;
            float2 lo = { acc[mt * 4 + nt][0], acc[mt * 4 + nt][1] };
            float2 hi = { acc[mt * 4 + nt][2], acc[mt * 4 + nt][3] };
            *(float2*)(C + (size_t)row * N + col) = lo;
            *(float2*)(C + (size_t)(row + 8) * N + col) = hi;
        }
    }
}

// ---------------- RoPE on a column-slice of the fused qkv buffer ------------
__global__ void rope_kernel(float* __restrict__ X, int rowstride, int coloff,
                            int nh, int total)
{
    int idx = blockIdx.x * blockDim.x + threadIdx.x;
    if (idx >= total) return;
    int j = idx & 63;
    int rest = idx >> 6;
    int hh = rest % nh;
    int row = rest / nh;
    int t = row & (T_ - 1);

    float inv = 1.0f / powf(10000.0f, (float)j * (1.0f / 64.0f));
    float ang = (float)t * inv;
    float s, c;
    sincosf(ang, &s, &c);

    float* p = X + (size_t)row * rowstride + coloff + hh * D_ + 2 * j;
    float x0 = p[0], x1 = p[1];
    p[0] = tf32r(x0 * c - x1 * s);
    p[1] = tf32r(x0 * s + x1 * c);
}

// ---------------- Flash attention (causal, GQA), tf32 mma + cp.async --------
// grid (T/64, H, B), 256 threads = 8 warps. K/V double-buffered via cp.async.
#define FQ_STRIDE 132
#define FS_STRIDE 68
#define FV_STRIDE 68
#define F_QS   0
#define F_KS   (64 * FQ_STRIDE)                 // 2 stages
#define F_VR   (F_KS + 2 * 64 * FQ_STRIDE)      // 2 stages
#define F_VT   (F_VR + 2 * 64 * FQ_STRIDE)
#define F_S    (F_VT + 128 * FV_STRIDE)
#define F_ROWS (F_S + 64 * FS_STRIDE)
#define FLASH_SMEM_FLOATS (F_ROWS + 3 * 64)     // 55488 -> 221952 B

__global__ void __launch_bounds__(256, 1) flash_attn_kernel(
    const float* __restrict__ QKV, float* __restrict__ O)
{
    extern __shared__ float sm[];
    float* Qs = sm + F_QS;
    float* Ks0 = sm + F_KS;
    float* Vr0 = sm + F_VR;
    float* Vt = sm + F_VT;
    float* S  = sm + F_S;
    float* mrow = sm + F_ROWS;
    float* lrow = mrow + 64;
    float* arow = lrow + 64;
    const uint32_t smem_base = smem_u32(sm);

    const int tid = threadIdx.x;
    const int wid = tid >> 5, lid = tid & 31;
    const int g = lid >> 2, tig = lid & 3;
    const int qt = gridDim.x - 1 - blockIdx.x;     // heavy tiles first
    const int h = blockIdx.y, b = blockIdx.z;
    const int kvh = h >> 1;
    const int q0 = qt * 64;

    const float* Qg = QKV + (size_t)h * D_;                         // q cols
    const float* Kq = QKV + H_ * D_ + (size_t)kvh * D_;             // k cols
    const float* Vq = QKV + H_ * D_ + KVH_ * D_ + (size_t)kvh * D_; // v cols

    const int wr  = (wid >> 1) * 16;
    const int wcq = (wid & 1) * 32;
    const int wcv = (wid & 1) * 64;

    // prefetch K,V tile kt into stage kt&1 (64 rows x 32 float4 each)
    auto prefetch_kv = [&](int kt) {
        const int stage = kt & 1;
        const uint32_t kb = smem_base + (uint32_t)(F_KS + stage * 64 * FQ_STRIDE) * 4;
        const uint32_t vb = smem_base + (uint32_t)(F_VR + stage * 64 * FQ_STRIDE) * 4;
#pragma unroll
        for (int i = 0; i < 8; i++) {
            int f = i * 256 + tid;           // 0..2047 float4 slots
            int row = f >> 5, c16 = f & 31;  // row 0..63, float4 col 0..31
            size_t goff = (size_t)(b * T_ + kt * 64 + row) * QKVN + c16 * 4;
            uint32_t soff = (uint32_t)(row * FQ_STRIDE + c16 * 4) * 4;
            CP_ASYNC16(kb + soff, Kq + goff);
            CP_ASYNC16(vb + soff, Vq + goff);
        }
    };

    // load Q tile (pre-rounded tf32)
    {
        int r = tid >> 2, c0 = (tid & 3) * 8;
        const float4* src = (const float4*)(Qg + (size_t)(b * T_ + q0 + r) * QKVN) + c0;
        float4* dst = (float4*)(Qs + r * FQ_STRIDE) + c0;
#pragma unroll
        for (int i = 0; i < 8; i++) dst[i] = src[i];
    }
    if (tid < 64) { mrow[tid] = -INFINITY; lrow[tid] = 0.f; }

    prefetch_kv(0);
    CP_COMMIT();

    float oacc[8][4];
#pragma unroll
    for (int i = 0; i < 8; i++)
#pragma unroll
        for (int jj = 0; jj < 4; jj++) oacc[i][jj] = 0.f;

    const float scale = 0.08838834764831845f;

    for (int kt = 0; kt <= qt; kt++) {
        CP_WAIT(0);
        __syncthreads();             // K/V(kt) resident for all; prev PV done
        if (kt < qt) { prefetch_kv(kt + 1); }
        CP_COMMIT();

        const float* ks = Ks0 + (kt & 1) * 64 * FQ_STRIDE;
        const float* vr = Vr0 + (kt & 1) * 64 * FQ_STRIDE;

        // ---- QK^T: warp tile 16x32, K=128 in 16 steps
        float sacc[4][4];
#pragma unroll
        for (int nt = 0; nt < 4; nt++)
#pragma unroll
            for (int jj = 0; jj < 4; jj++) sacc[nt][jj] = 0.f;

#pragma unroll
        for (int ksi = 0; ksi < 16; ksi++) {
            const int k0 = ksi * 8;
            uint32_t a[4];
            const uint32_t* ap = (const uint32_t*)(Qs + (wr + g) * FQ_STRIDE + k0 + tig);
            a[0] = ap[0];
            a[1] = ap[8 * FQ_STRIDE];
            a[2] = ap[4];
            a[3] = ap[8 * FQ_STRIDE + 4];
#pragma unroll
            for (int nt = 0; nt < 4; nt++) {
                uint32_t bb[2];
                const uint32_t* bp = (const uint32_t*)(ks + (wcq + nt * 8 + g) * FQ_STRIDE + k0 + tig);
                bb[0] = bp[0];
                bb[1] = bp[4];
                mma_tf32(sacc[nt], a, bb);
            }
        }
        // mask + scale + store S
        {
            const bool diag = (kt == qt);
            const int gi0 = wr + g, gi1 = wr + g + 8;
#pragma unroll
            for (int nt = 0; nt < 4; nt++) {
                int gj = wcq + nt * 8 + 2 * tig;
                float s0 = sacc[nt][0] * scale;
                float s1 = sacc[nt][1] * scale;
                float s2 = sacc[nt][2] * scale;
                float s3 = sacc[nt][3] * scale;
                if (diag) {
                    if (gj     > gi0) s0 = -1e30f;
                    if (gj + 1 > gi0) s1 = -1e30f;
                    if (gj     > gi1) s2 = -1e30f;
                    if (gj + 1 > gi1) s3 = -1e30f;
                }
                *(float2*)(S + gi0 * FS_STRIDE + gj) = make_float2(s0, s1);
                *(float2*)(S + gi1 * FS_STRIDE + gj) = make_float2(s2, s3);
            }
        }
        __syncthreads();

        // ---- online softmax (4 threads/row)
        {
            int row = tid >> 2, qq = tid & 3;
            float* srow = S + row * FS_STRIDE + qq * 16;
            float mx = -INFINITY;
#pragma unroll
            for (int j = 0; j < 16; j++) mx = fmaxf(mx, srow[j]);
            mx = fmaxf(mx, __shfl_xor_sync(0xFFFFFFFF, mx, 1));
            mx = fmaxf(mx, __shfl_xor_sync(0xFFFFFFFF, mx, 2));
            float m_old = mrow[row];
            mx = fmaxf(mx, m_old);
            float sum = 0.f;
#pragma unroll
            for (int j = 0; j < 16; j++) {
                float p = tf32r(__expf(srow[j] - mx));
                srow[j] = p;
                sum += p;
            }
            sum += __shfl_xor_sync(0xFFFFFFFF, sum, 1);
            sum += __shfl_xor_sync(0xFFFFFFFF, sum, 2);
            if (qq == 0) {
                float al = __expf(m_old - mx);
                lrow[row] = lrow[row] * al + sum;
                mrow[row] = mx;
                arow[row] = al;
            }
        }
        // transpose V raw -> Vt (with tf32 rounding)
        {
            int s = tid >> 2, qq = tid & 3;
            const float* vsrc = vr + s * FQ_STRIDE + qq * 32;
#pragma unroll
            for (int i = 0; i < 32; i += 4) {
                float4 t = *(const float4*)(vsrc + i);
                int d0 = qq * 32 + i;
                Vt[(d0 + 0) * FV_STRIDE + s] = tf32r(t.x);
                Vt[(d0 + 1) * FV_STRIDE + s] = tf32r(t.y);
                Vt[(d0 + 2) * FV_STRIDE + s] = tf32r(t.z);
                Vt[(d0 + 3) * FV_STRIDE + s] = tf32r(t.w);
            }
        }
        __syncthreads();

        // ---- PV: warp tile 16x64, K=64 in 8 steps
        {
            float al0 = arow[wr + g], al1 = arow[wr + g + 8];
#pragma unroll
            for (int nt = 0; nt < 8; nt++) {
                oacc[nt][0] *= al0; oacc[nt][1] *= al0;
                oacc[nt][2] *= al1; oacc[nt][3] *= al1;
            }
#pragma unroll
            for (int ksi = 0; ksi < 8; ksi++) {
                const int k0 = ksi * 8;
                uint32_t a[4];
                const uint32_t* ap = (const uint32_t*)(S + (wr + g) * FS_STRIDE + k0 + tig);
                a[0] = ap[0];
                a[1] = ap[8 * FS_STRIDE];
                a[2] = ap[4];
                a[3] = ap[8 * FS_STRIDE + 4];
#pragma unroll
                for (int nt = 0; nt < 8; nt++) {
                    uint32_t bb[2];
                    const uint32_t* bp = (const uint32_t*)(Vt + (wcv + nt * 8 + g) * FV_STRIDE + k0 + tig);
                    bb[0] = bp[0];
                    bb[1] = bp[4];
                    mma_tf32(oacc[nt], a, bb);
                }
            }
        }
    }

    // epilogue
    {
        float il0 = 1.f / lrow[wr + g];
        float il1 = 1.f / lrow[wr + g + 8];
        float* O0 = O + (size_t)(b * T_ + q0 + wr + g) * (H_ * D_) + h * D_;
        float* O1 = O + (size_t)(b * T_ + q0 + wr + g + 8) * (H_ * D_) + h * D_;
#pragma unroll
        for (int nt = 0; nt < 8; nt++) {
            int col = wcv + nt * 8 + 2 * tig;
            *(float2*)(O0 + col) = make_float2(tf32r(oacc[nt][0] * il0), tf32r(oacc[nt][1] * il0));
            *(float2*)(O1 + col) = make_float2(tf32r(oacc[nt][2] * il1), tf32r(oacc[nt][3] * il1));
        }
    }
}

// -------------------------------- launch -------------------------------------
extern "C" void kernel_launch(void* const* d_in, const int* in_sizes, int n_in,
                              void* d_out, int out_size)
{
    const float* x  = (const float*)d_in[0];
    const float* wq = (const float*)d_in[2];
    const float* wk = (const float*)d_in[3];
    const float* wv = (const float*)d_in[4];
    const float* wo = (const float*)d_in[5];
    float* out = (float*)d_out;

    float *qkv, *o, *xr, *wqkvt, *wot;
    cudaGetSymbolAddress((void**)&qkv, g_qkv);
    cudaGetSymbolAddress((void**)&o, g_o);
    cudaGetSymbolAddress((void**)&xr, g_xr);
    cudaGetSymbolAddress((void**)&wqkvt, g_wqkvt);
    cudaGetSymbolAddress((void**)&wot, g_wot);

    // tf32-round x; transpose+round weights into fused buffer
    round_tf32_kernel<<<(ROWS_ * E_ / 4 + 255) / 256, 256>>>(x, xr, ROWS_ * E_ / 4);
    dim3 tb(32, 8);
    transpose_kernel<<<dim3((H_ * D_) / 32, E_ / 32), tb>>>(
        wq, wqkvt, E_, H_ * D_);
    transpose_kernel<<<dim3((KVH_ * D_) / 32, E_ / 32), tb>>>(
        wk, wqkvt + (size_t)(H_ * D_) * E_, E_, KVH_ * D_);
    transpose_kernel<<<dim3((KVH_ * D_) / 32, E_ / 32), tb>>>(
        wv, wqkvt + (size_t)(H_ * D_ + KVH_ * D_) * E_, E_, KVH_ * D_);
    transpose_kernel<<<dim3(E_ / 32, (H_ * D_) / 32), tb>>>(wo, wot, H_ * D_, E_);

    cudaFuncSetAttribute(tc_gemm_kernel,
                         cudaFuncAttributeMaxDynamicSharedMemorySize, GSMEM_BYTES);

    // Fused QKV projection: [4096, 2048] @ [2048, 4096]
    tc_gemm_kernel<<<dim3(QKVN / 128, ROWS_ / 128), 256, GSMEM_BYTES>>>(
        ROWS_, QKVN, E_, xr, wqkvt, qkv);

    // RoPE on q and k slices of fused buffer
    {
        int total_q = ROWS_ * H_ * 64;
        int total_k = ROWS_ * KVH_ * 64;
        rope_kernel<<<(total_q + 255) / 256, 256>>>(qkv, QKVN, 0, H_, total_q);
        rope_kernel<<<(total_k + 255) / 256, 256>>>(qkv, QKVN, H_ * D_, KVH_, total_k);
    }

    // Flash attention
    {
        int smem_bytes = FLASH_SMEM_FLOATS * (int)sizeof(float);
        cudaFuncSetAttribute(flash_attn_kernel,
                             cudaFuncAttributeMaxDynamicSharedMemorySize, smem_bytes);
        flash_attn_kernel<<<dim3(T_ / 64, H_, B_), 256, smem_bytes>>>(qkv, o);
    }

    // Output projection
    tc_gemm_kernel<<<dim3(E_ / 128, ROWS_ / 128), 256, GSMEM_BYTES>>>(
        ROWS_, E_, H_ * D_, o, wot, out);
}

// round 7
// speedup vs baseline: 6.2249x; 1.0586x over previous
#include <cuda_runtime.h>
#include <cuda_bf16.h>
#include <math.h>
#include <cstdint>

// Problem constants
#define B_  2
#define T_  2048
#define E_  2048
#define H_  16
#define KVH_ 8
#define D_  128
#define ROWS_ (B_ * T_)            // 4096
#define QKVN (H_ * D_ + 2 * KVH_ * D_)   // 4096 fused N
#define VOFF (H_ * D_ + KVH_ * D_)       // 3072: v column offset in fused buffer

// ---------------- scratch (device globals; no allocs allowed) ----------------
__device__ float g_qkv[(size_t)ROWS_ * QKVN];      // fused q|k|v
__device__ float g_o[(size_t)ROWS_ * H_ * D_];     // attn out
__device__ float g_xr[(size_t)ROWS_ * E_];         // tf32-rounded x
__device__ float g_wqkvt[(size_t)QKVN * E_];       // [wq|wk|wv]^T rows, tf32
__device__ float g_wot[(size_t)E_ * H_ * D_];

// ====================== helpers ======================
__device__ __forceinline__ uint32_t smem_u32(const void* p) {
    uint32_t a;
    asm("{ .reg .u64 t; cvta.to.shared.u64 t, %1; cvt.u32.u64 %0, t; }" : "=r"(a) : "l"(p));
    return a;
}
#define CP_ASYNC16(dst, src) \
    asm volatile("cp.async.cg.shared.global [%0], [%1], 16;" :: "r"(dst), "l"(src))
#define CP_COMMIT() asm volatile("cp.async.commit_group;" ::: "memory")
#define CP_WAIT(n)  asm volatile("cp.async.wait_group %0;" :: "n"(n) : "memory")

__device__ __forceinline__ uint32_t f2tf32(float x) {
    uint32_t u;
    asm("cvt.rna.tf32.f32 %0, %1;" : "=r"(u) : "f"(x));
    return u;
}
__device__ __forceinline__ float tf32r(float x) {
    return __uint_as_float(f2tf32(x));
}
__device__ __forceinline__ void mma_tf32(float (&c)[4], const uint32_t (&a)[4],
                                         const uint32_t (&b)[2]) {
    asm volatile(
        "mma.sync.aligned.m16n8k8.row.col.f32.tf32.tf32.f32 "
        "{%0,%1,%2,%3}, {%4,%5,%6,%7}, {%8,%9}, {%0,%1,%2,%3};"
        : "+f"(c[0]), "+f"(c[1]), "+f"(c[2]), "+f"(c[3])
        : "r"(a[0]), "r"(a[1]), "r"(a[2]), "r"(a[3]), "r"(b[0]), "r"(b[1]));
}

// ============== round x to tf32 ==============
__global__ void round_tf32_kernel(const float* __restrict__ in, float* __restrict__ out,
                                  int n4)
{
    int i = blockIdx.x * blockDim.x + threadIdx.x;
    if (i >= n4) return;
    float4 t = ((const float4*)in)[i];
    t.x = tf32r(t.x); t.y = tf32r(t.y); t.z = tf32r(t.z); t.w = tf32r(t.w);
    ((float4*)out)[i] = t;
}

// ============== round v-slice of fused qkv buffer to tf32 (in place) ==========
// rows = ROWS_, cols [VOFF, VOFF+1024) floats; 256 float4 per row.
__global__ void vround_kernel(float* __restrict__ X)
{
    int idx = blockIdx.x * blockDim.x + threadIdx.x;
    int row = idx >> 8, c4 = idx & 255;
    float4* p = (float4*)(X + (size_t)row * QKVN + VOFF) + c4;
    float4 t = *p;
    t.x = tf32r(t.x); t.y = tf32r(t.y); t.z = tf32r(t.z); t.w = tf32r(t.w);
    *p = t;
}

// ============ weight transpose: Wt[N,K] = tf32(W[K,N]) ============
__global__ void transpose_kernel(const float* __restrict__ W, float* __restrict__ Wt,
                                 int K, int N)
{
    __shared__ float tile[32][33];
    int bx = blockIdx.x * 32;  // n
    int by = blockIdx.y * 32;  // k
    int tx = threadIdx.x, ty = threadIdx.y;
#pragma unroll
    for (int j = 0; j < 32; j += 8)
        tile[ty + j][tx] = W[(size_t)(by + ty + j) * N + bx + tx];
    __syncthreads();
#pragma unroll
    for (int j = 0; j < 32; j += 8)
        Wt[(size_t)(bx + ty + j) * K + by + tx] = tf32r(tile[tx][ty + j]);
}

// ====================== tf32 mma.sync GEMM ======================
// C[M,N] = A[M,K] @ Bt[N,K]^T.  CTA tile 128x128, BK=16, 3-stage cp.async,
// 2 CTAs/SM. 256 threads = 8 warps; warp tile 64x32.
#define GBM 128
#define GBN 128
#define GBK 16
#define GSTRIDE 20
#define GSTAGE_FLOATS (2 * GBM * GSTRIDE)
#define GSTAGES 3
#define GSMEM_BYTES (GSTAGES * GSTAGE_FLOATS * 4)   // 61440

__global__ void __launch_bounds__(256, 2) tc_gemm_kernel(
    int M, int N, int K,
    const float* __restrict__ A, const float* __restrict__ Bt,
    float* __restrict__ C)
{
    extern __shared__ float smf[];
    const uint32_t smem_base = smem_u32(smf);
    const int tid = threadIdx.x;
    const int wid = tid >> 5, lid = tid & 31;
    const int g = lid >> 2, tig = lid & 3;

    const int m0 = blockIdx.y * GBM;
    const int n0 = blockIdx.x * GBN;
    const float* Ab = A  + (size_t)m0 * K;
    const float* Bb = Bt + (size_t)n0 * K;
    const int nchunks = K / GBK;

    const int wm0 = (wid >> 2) * 64;
    const int wn0 = (wid & 3) * 32;

    float acc[16][4];
#pragma unroll
    for (int i = 0; i < 16; i++)
#pragma unroll
        for (int jj = 0; jj < 4; jj++) acc[i][jj] = 0.f;

    auto load_chunk = [&](int j) {
        const int stage = j % GSTAGES;
        const uint32_t abase = smem_base + stage * GSTAGE_FLOATS * 4;
        const uint32_t bbase = abase + GBM * GSTRIDE * 4;
        const float* ag = Ab + j * GBK;
        const float* bg = Bb + j * GBK;
#pragma unroll
        for (int i = 0; i < 2; i++) {
            int f = i * 256 + tid;
            int row = f >> 2, c = f & 3;
            uint32_t soff = (uint32_t)(row * GSTRIDE + c * 4) * 4;
            CP_ASYNC16(abase + soff, ag + (size_t)row * K + c * 4);
            CP_ASYNC16(bbase + soff, bg + (size_t)row * K + c * 4);
        }
    };

#pragma unroll
    for (int j = 0; j < GSTAGES - 1; j++) { load_chunk(j); CP_COMMIT(); }

    for (int j = 0; j < nchunks; j++) {
        CP_WAIT(GSTAGES - 2);
        __syncthreads();
        int pf = j + GSTAGES - 1;
        if (pf < nchunks) load_chunk(pf);
        CP_COMMIT();

        const int stage = j % GSTAGES;
        const float* as = smf + stage * GSTAGE_FLOATS;
        const float* bs = as + GBM * GSTRIDE;

#pragma unroll
        for (int ks = 0; ks < 2; ks++) {
            const int k0 = ks * 8;
            uint32_t afr[4][4], bfr[4][2];
#pragma unroll
            for (int mt = 0; mt < 4; mt++) {
                const uint32_t* ap = (const uint32_t*)(as + (wm0 + mt * 16 + g) * GSTRIDE + k0 + tig);
                afr[mt][0] = ap[0];
                afr[mt][1] = ap[8 * GSTRIDE];
                afr[mt][2] = ap[4];
                afr[mt][3] = ap[8 * GSTRIDE + 4];
            }
#pragma unroll
            for (int nt = 0; nt < 4; nt++) {
                const uint32_t* bp = (const uint32_t*)(bs + (wn0 + nt * 8 + g) * GSTRIDE + k0 + tig);
                bfr[nt][0] = bp[0];
                bfr[nt][1] = bp[4];
            }
#pragma unroll
            for (int mt = 0; mt < 4; mt++)
#pragma unroll
                for (int nt = 0; nt < 4; nt++)
                    mma_tf32(acc[mt * 4 + nt], afr[mt], bfr[nt]);
        }
        __syncthreads();
    }

#pragma unroll
    for (int mt = 0; mt < 4; mt++) {
#pragma unroll
        for (int nt = 0; nt < 4; nt++) {
            int row = m0 + wm0 + mt * 16 + g;
            int col = n0 + wn0 + nt * 8 + tig * 2;
            float2 lo = { acc[mt * 4 + nt][0], acc[mt * 4 + nt][1] };
            float2 hi = { acc[mt * 4 + nt][2], acc[mt * 4 + nt][3] };
            *(float2*)(C + (size_t)row * N + col) = lo;
            *(float2*)(C + (size_t)(row + 8) * N + col) = hi;
        }
    }
}

// ---------------- RoPE on a column-slice of the fused qkv buffer ------------
__global__ void rope_kernel(float* __restrict__ X, int rowstride, int coloff,
                            int nh, int total)
{
    int idx = blockIdx.x * blockDim.x + threadIdx.x;
    if (idx >= total) return;
    int j = idx & 63;
    int rest = idx >> 6;
    int hh = rest % nh;
    int row = rest / nh;
    int t = row & (T_ - 1);

    float inv = 1.0f / powf(10000.0f, (float)j * (1.0f / 64.0f));
    float ang = (float)t * inv;
    float s, c;
    sincosf(ang, &s, &c);

    float* p = X + (size_t)row * rowstride + coloff + hh * D_ + 2 * j;
    float x0 = p[0], x1 = p[1];
    p[0] = tf32r(x0 * c - x1 * s);
    p[1] = tf32r(x0 * s + x1 * c);
}

// ---------------- Flash attention (causal, GQA), tf32 mma + cp.async --------
// grid (T/64, H, B), 256 threads = 8 warps. K/V double-buffered via cp.async.
// V used directly as mma B operand in [seq][d] layout (no transpose).
#define FQ_STRIDE 132
#define FS_STRIDE 68
#define F_QS   0
#define F_KS   (64 * FQ_STRIDE)                 // 2 stages
#define F_VR   (F_KS + 2 * 64 * FQ_STRIDE)      // 2 stages
#define F_S    (F_VR + 2 * 64 * FQ_STRIDE)
#define F_ROWS (F_S + 64 * FS_STRIDE)
#define FLASH_SMEM_FLOATS (F_ROWS + 3 * 64)     // 46784 -> 187136 B

__global__ void __launch_bounds__(256, 1) flash_attn_kernel(
    const float* __restrict__ QKV, float* __restrict__ O)
{
    extern __shared__ float sm[];
    float* Qs = sm + F_QS;
    float* Ks0 = sm + F_KS;
    float* Vr0 = sm + F_VR;
    float* S  = sm + F_S;
    float* mrow = sm + F_ROWS;
    float* lrow = mrow + 64;
    float* arow = lrow + 64;
    const uint32_t smem_base = smem_u32(sm);

    const int tid = threadIdx.x;
    const int wid = tid >> 5, lid = tid & 31;
    const int g = lid >> 2, tig = lid & 3;
    const int qt = gridDim.x - 1 - blockIdx.x;     // heavy tiles first
    const int h = blockIdx.y, b = blockIdx.z;
    const int kvh = h >> 1;
    const int q0 = qt * 64;

    const float* Qg = QKV + (size_t)h * D_;                         // q cols
    const float* Kq = QKV + H_ * D_ + (size_t)kvh * D_;             // k cols
    const float* Vq = QKV + VOFF + (size_t)kvh * D_;                // v cols

    const int wr  = (wid >> 1) * 16;
    const int wcq = (wid & 1) * 32;
    const int wcv = (wid & 1) * 64;

    // prefetch K,V tile kt into stage kt&1 (64 rows x 32 float4 each)
    auto prefetch_kv = [&](int kt) {
        const int stage = kt & 1;
        const uint32_t kb = smem_base + (uint32_t)(F_KS + stage * 64 * FQ_STRIDE) * 4;
        const uint32_t vb = smem_base + (uint32_t)(F_VR + stage * 64 * FQ_STRIDE) * 4;
#pragma unroll
        for (int i = 0; i < 8; i++) {
            int f = i * 256 + tid;           // 0..2047 float4 slots
            int row = f >> 5, c16 = f & 31;  // row 0..63, float4 col 0..31
            size_t goff = (size_t)(b * T_ + kt * 64 + row) * QKVN + c16 * 4;
            uint32_t soff = (uint32_t)(row * FQ_STRIDE + c16 * 4) * 4;
            CP_ASYNC16(kb + soff, Kq + goff);
            CP_ASYNC16(vb + soff, Vq + goff);
        }
    };

    // load Q tile (pre-rounded tf32)
    {
        int r = tid >> 2, c0 = (tid & 3) * 8;
        const float4* src = (const float4*)(Qg + (size_t)(b * T_ + q0 + r) * QKVN) + c0;
        float4* dst = (float4*)(Qs + r * FQ_STRIDE) + c0;
#pragma unroll
        for (int i = 0; i < 8; i++) dst[i] = src[i];
    }
    if (tid < 64) { mrow[tid] = -INFINITY; lrow[tid] = 0.f; }

    prefetch_kv(0);
    CP_COMMIT();

    float oacc[8][4];
#pragma unroll
    for (int i = 0; i < 8; i++)
#pragma unroll
        for (int jj = 0; jj < 4; jj++) oacc[i][jj] = 0.f;

    const float scale = 0.08838834764831845f;

    for (int kt = 0; kt <= qt; kt++) {
        CP_WAIT(0);
        __syncthreads();             // K/V(kt) resident for all; prev PV done
        if (kt < qt) { prefetch_kv(kt + 1); }
        CP_COMMIT();

        const float* ks = Ks0 + (kt & 1) * 64 * FQ_STRIDE;
        const float* vr = Vr0 + (kt & 1) * 64 * FQ_STRIDE;

        // ---- QK^T: warp tile 16x32, K=128 in 16 steps
        float sacc[4][4];
#pragma unroll
        for (int nt = 0; nt < 4; nt++)
#pragma unroll
            for (int jj = 0; jj < 4; jj++) sacc[nt][jj] = 0.f;

#pragma unroll
        for (int ksi = 0; ksi < 16; ksi++) {
            const int k0 = ksi * 8;
            uint32_t a[4];
            const uint32_t* ap = (const uint32_t*)(Qs + (wr + g) * FQ_STRIDE + k0 + tig);
            a[0] = ap[0];
            a[1] = ap[8 * FQ_STRIDE];
            a[2] = ap[4];
            a[3] = ap[8 * FQ_STRIDE + 4];
#pragma unroll
            for (int nt = 0; nt < 4; nt++) {
                uint32_t bb[2];
                const uint32_t* bp = (const uint32_t*)(ks + (wcq + nt * 8 + g) * FQ_STRIDE + k0 + tig);
                bb[0] = bp[0];
                bb[1] = bp[4];
                mma_tf32(sacc[nt], a, bb);
            }
        }
        // mask + scale + store S
        {
            const bool diag = (kt == qt);
            const int gi0 = wr + g, gi1 = wr + g + 8;
#pragma unroll
            for (int nt = 0; nt < 4; nt++) {
                int gj = wcq + nt * 8 + 2 * tig;
                float s0 = sacc[nt][0] * scale;
                float s1 = sacc[nt][1] * scale;
                float s2 = sacc[nt][2] * scale;
                float s3 = sacc[nt][3] * scale;
                if (diag) {
                    if (gj     > gi0) s0 = -1e30f;
                    if (gj + 1 > gi0) s1 = -1e30f;
                    if (gj     > gi1) s2 = -1e30f;
                    if (gj + 1 > gi1) s3 = -1e30f;
                }
                *(float2*)(S + gi0 * FS_STRIDE + gj) = make_float2(s0, s1);
                *(float2*)(S + gi1 * FS_STRIDE + gj) = make_float2(s2, s3);
            }
        }
        __syncthreads();

        // ---- online softmax (4 threads/row)
        {
            int row = tid >> 2, qq = tid & 3;
            float* srow = S + row * FS_STRIDE + qq * 16;
            float mx = -INFINITY;
#pragma unroll
            for (int j = 0; j < 16; j++) mx = fmaxf(mx, srow[j]);
            mx = fmaxf(mx, __shfl_xor_sync(0xFFFFFFFF, mx, 1));
            mx = fmaxf(mx, __shfl_xor_sync(0xFFFFFFFF, mx, 2));
            float m_old = mrow[row];
            mx = fmaxf(mx, m_old);
            float sum = 0.f;
#pragma unroll
            for (int j = 0; j < 16; j++) {
                float p = tf32r(__expf(srow[j] - mx));
                srow[j] = p;
                sum += p;
            }
            sum += __shfl_xor_sync(0xFFFFFFFF, sum, 1);
            sum += __shfl_xor_sync(0xFFFFFFFF, sum, 2);
            if (qq == 0) {
                float al = __expf(m_old - mx);
                lrow[row] = lrow[row] * al + sum;
                mrow[row] = mx;
                arow[row] = al;
            }
        }
        __syncthreads();

        // ---- PV: warp tile 16x64, K=64 in 8 steps; B = raw V [seq][d]
        {
            float al0 = arow[wr + g], al1 = arow[wr + g + 8];
#pragma unroll
            for (int nt = 0; nt < 8; nt++) {
                oacc[nt][0] *= al0; oacc[nt][1] *= al0;
                oacc[nt][2] *= al1; oacc[nt][3] *= al1;
            }
#pragma unroll
            for (int ksi = 0; ksi < 8; ksi++) {
                const int k0 = ksi * 8;
                uint32_t a[4];
                const uint32_t* ap = (const uint32_t*)(S + (wr + g) * FS_STRIDE + k0 + tig);
                a[0] = ap[0];
                a[1] = ap[8 * FS_STRIDE];
                a[2] = ap[4];
                a[3] = ap[8 * FS_STRIDE + 4];
                // b fragment from raw V: b0 = V[k0+tig][col], b1 = V[k0+tig+4][col]
                const uint32_t* vb = (const uint32_t*)(vr + (k0 + tig) * FQ_STRIDE);
#pragma unroll
                for (int nt = 0; nt < 8; nt++) {
                    int col = wcv + nt * 8 + g;
                    uint32_t bb[2];
                    bb[0] = vb[col];
                    bb[1] = vb[4 * FQ_STRIDE + col];
                    mma_tf32(oacc[nt], a, bb);
                }
            }
        }
    }

    // epilogue
    {
        float il0 = 1.f / lrow[wr + g];
        float il1 = 1.f / lrow[wr + g + 8];
        float* O0 = O + (size_t)(b * T_ + q0 + wr + g) * (H_ * D_) + h * D_;
        float* O1 = O + (size_t)(b * T_ + q0 + wr + g + 8) * (H_ * D_) + h * D_;
#pragma unroll
        for (int nt = 0; nt < 8; nt++) {
            int col = wcv + nt * 8 + 2 * tig;
            *(float2*)(O0 + col) = make_float2(tf32r(oacc[nt][0] * il0), tf32r(oacc[nt][1] * il0));
            *(float2*)(O1 + col) = make_float2(tf32r(oacc[nt][2] * il1), tf32r(oacc[nt][3] * il1));
        }
    }
}

// -------------------------------- launch -------------------------------------
extern "C" void kernel_launch(void* const* d_in, const int* in_sizes, int n_in,
                              void* d_out, int out_size)
{
    const float* x  = (const float*)d_in[0];
    const float* wq = (const float*)d_in[2];
    const float* wk = (const float*)d_in[3];
    const float* wv = (const float*)d_in[4];
    const float* wo = (const float*)d_in[5];
    float* out = (float*)d_out;

    float *qkv, *o, *xr, *wqkvt, *wot;
    cudaGetSymbolAddress((void**)&qkv, g_qkv);
    cudaGetSymbolAddress((void**)&o, g_o);
    cudaGetSymbolAddress((void**)&xr, g_xr);
    cudaGetSymbolAddress((void**)&wqkvt, g_wqkvt);
    cudaGetSymbolAddress((void**)&wot, g_wot);

    dim3 tb(32, 8);
    // Launches 0..4: round x + qkv weight transposes  (5th launch = QKV GEMM -> ncu target)
    round_tf32_kernel<<<(ROWS_ * E_ / 4 + 255) / 256, 256>>>(x, xr, ROWS_ * E_ / 4);
    transpose_kernel<<<dim3((H_ * D_) / 32, E_ / 32), tb>>>(
        wq, wqkvt, E_, H_ * D_);
    transpose_kernel<<<dim3((KVH_ * D_) / 32, E_ / 32), tb>>>(
        wk, wqkvt + (size_t)(H_ * D_) * E_, E_, KVH_ * D_);
    transpose_kernel<<<dim3((KVH_ * D_) / 32, E_ / 32), tb>>>(
        wv, wqkvt + (size_t)(H_ * D_ + KVH_ * D_) * E_, E_, KVH_ * D_);

    cudaFuncSetAttribute(tc_gemm_kernel,
                         cudaFuncAttributeMaxDynamicSharedMemorySize, GSMEM_BYTES);

    // Fused QKV projection: [4096, 2048] @ [2048, 4096]
    tc_gemm_kernel<<<dim3(QKVN / 128, ROWS_ / 128), 256, GSMEM_BYTES>>>(
        ROWS_, QKVN, E_, xr, wqkvt, qkv);

    // RoPE on q and k slices; round v slice to tf32
    {
        int total_q = ROWS_ * H_ * 64;
        int total_k = ROWS_ * KVH_ * 64;
        rope_kernel<<<(total_q + 255) / 256, 256>>>(qkv, QKVN, 0, H_, total_q);
        rope_kernel<<<(total_k + 255) / 256, 256>>>(qkv, QKVN, H_ * D_, KVH_, total_k);
        vround_kernel<<<(ROWS_ * 256) / 256, 256>>>(qkv);
    }

    // Flash attention
    {
        int smem_bytes = FLASH_SMEM_FLOATS * (int)sizeof(float);
        cudaFuncSetAttribute(flash_attn_kernel,
                             cudaFuncAttributeMaxDynamicSharedMemorySize, smem_bytes);
        flash_attn_kernel<<<dim3(T_ / 64, H_, B_), 256, smem_bytes>>>(qkv, o);
    }

    // wo transpose (moved here; only needed by out-proj)
    transpose_kernel<<<dim3(E_ / 32, (H_ * D_) / 32), tb>>>(wo, wot, H_ * D_, E_);

    // Output projection
    tc_gemm_kernel<<<dim3(E_ / 128, ROWS_ / 128), 256, GSMEM_BYTES>>>(
        ROWS_, E_, H_ * D_, o, wot, out);
}

// round 8
// speedup vs baseline: 6.6492x; 1.0682x over previous
#include <cuda_runtime.h>
#include <cuda_bf16.h>
#include <math.h>
#include <cstdint>

// Problem constants
#define B_  2
#define T_  2048
#define E_  2048
#define H_  16
#define KVH_ 8
#define D_  128
#define ROWS_ (B_ * T_)            // 4096
#define QKVN (H_ * D_ + 2 * KVH_ * D_)   // 4096 fused N
#define VOFF (H_ * D_ + KVH_ * D_)       // 3072: v column offset in fused buffer

// ---------------- scratch (device globals; no allocs allowed) ----------------
__device__ float g_qkv[(size_t)ROWS_ * QKVN];      // fused q|k|v
__device__ float g_o[(size_t)ROWS_ * H_ * D_];     // attn out
__device__ float g_xr[(size_t)ROWS_ * E_];         // tf32-rounded x
__device__ float g_wqkvt[(size_t)QKVN * E_];       // [wq|wk|wv]^T rows, tf32
__device__ float g_wot[(size_t)E_ * H_ * D_];

// ====================== helpers ======================
__device__ __forceinline__ uint32_t smem_u32(const void* p) {
    uint32_t a;
    asm("{ .reg .u64 t; cvta.to.shared.u64 t, %1; cvt.u32.u64 %0, t; }" : "=r"(a) : "l"(p));
    return a;
}
#define CP_ASYNC16(dst, src) \
    asm volatile("cp.async.cg.shared.global [%0], [%1], 16;" :: "r"(dst), "l"(src))
#define CP_COMMIT() asm volatile("cp.async.commit_group;" ::: "memory")
#define CP_WAIT(n)  asm volatile("cp.async.wait_group %0;" :: "n"(n) : "memory")

__device__ __forceinline__ uint32_t f2tf32(float x) {
    uint32_t u;
    asm("cvt.rna.tf32.f32 %0, %1;" : "=r"(u) : "f"(x));
    return u;
}
__device__ __forceinline__ float tf32r(float x) {
    return __uint_as_float(f2tf32(x));
}
__device__ __forceinline__ void mma_tf32(float (&c)[4], const uint32_t (&a)[4],
                                         const uint32_t (&b)[2]) {
    asm volatile(
        "mma.sync.aligned.m16n8k8.row.col.f32.tf32.tf32.f32 "
        "{%0,%1,%2,%3}, {%4,%5,%6,%7}, {%8,%9}, {%0,%1,%2,%3};"
        : "+f"(c[0]), "+f"(c[1]), "+f"(c[2]), "+f"(c[3])
        : "r"(a[0]), "r"(a[1]), "r"(a[2]), "r"(a[3]), "r"(b[0]), "r"(b[1]));
}

// ============== round x to tf32 ==============
__global__ void round_tf32_kernel(const float* __restrict__ in, float* __restrict__ out,
                                  int n4)
{
    int i = blockIdx.x * blockDim.x + threadIdx.x;
    if (i >= n4) return;
    float4 t = ((const float4*)in)[i];
    t.x = tf32r(t.x); t.y = tf32r(t.y); t.z = tf32r(t.z); t.w = tf32r(t.w);
    ((float4*)out)[i] = t;
}

// ============== round v-slice of fused qkv buffer to tf32 (in place) ==========
__global__ void vround_kernel(float* __restrict__ X)
{
    int idx = blockIdx.x * blockDim.x + threadIdx.x;
    int row = idx >> 8, c4 = idx & 255;
    float4* p = (float4*)(X + (size_t)row * QKVN + VOFF) + c4;
    float4 t = *p;
    t.x = tf32r(t.x); t.y = tf32r(t.y); t.z = tf32r(t.z); t.w = tf32r(t.w);
    *p = t;
}

// ============ weight transpose: Wt[N,K] = tf32(W[K,N]) ============
__global__ void transpose_kernel(const float* __restrict__ W, float* __restrict__ Wt,
                                 int K, int N)
{
    __shared__ float tile[32][33];
    int bx = blockIdx.x * 32;  // n
    int by = blockIdx.y * 32;  // k
    int tx = threadIdx.x, ty = threadIdx.y;
#pragma unroll
    for (int j = 0; j < 32; j += 8)
        tile[ty + j][tx] = W[(size_t)(by + ty + j) * N + bx + tx];
    __syncthreads();
#pragma unroll
    for (int j = 0; j < 32; j += 8)
        Wt[(size_t)(bx + ty + j) * K + by + tx] = tf32r(tile[tx][ty + j]);
}

// ====================== tf32 mma.sync GEMM ======================
// C[M,N] = A[M,K] @ Bt[N,K]^T.  CTA tile 128x128, BK=16, 3-stage cp.async,
// 2 CTAs/SM. 256 threads = 8 warps; warp tile 64x32.
#define GBM 128
#define GBN 128
#define GBK 16
#define GSTRIDE 20
#define GSTAGE_FLOATS (2 * GBM * GSTRIDE)
#define GSTAGES 3
#define GSMEM_BYTES (GSTAGES * GSTAGE_FLOATS * 4)   // 61440

__global__ void __launch_bounds__(256, 2) tc_gemm_kernel(
    int M, int N, int K,
    const float* __restrict__ A, const float* __restrict__ Bt,
    float* __restrict__ C)
{
    extern __shared__ float smf[];
    const uint32_t smem_base = smem_u32(smf);
    const int tid = threadIdx.x;
    const int wid = tid >> 5, lid = tid & 31;
    const int g = lid >> 2, tig = lid & 3;

    const int m0 = blockIdx.y * GBM;
    const int n0 = blockIdx.x * GBN;
    const float* Ab = A  + (size_t)m0 * K;
    const float* Bb = Bt + (size_t)n0 * K;
    const int nchunks = K / GBK;

    const int wm0 = (wid >> 2) * 64;
    const int wn0 = (wid & 3) * 32;

    float acc[16][4];
#pragma unroll
    for (int i = 0; i < 16; i++)
#pragma unroll
        for (int jj = 0; jj < 4; jj++) acc[i][jj] = 0.f;

    auto load_chunk = [&](int j) {
        const int stage = j % GSTAGES;
        const uint32_t abase = smem_base + stage * GSTAGE_FLOATS * 4;
        const uint32_t bbase = abase + GBM * GSTRIDE * 4;
        const float* ag = Ab + j * GBK;
        const float* bg = Bb + j * GBK;
#pragma unroll
        for (int i = 0; i < 2; i++) {
            int f = i * 256 + tid;
            int row = f >> 2, c = f & 3;
            uint32_t soff = (uint32_t)(row * GSTRIDE + c * 4) * 4;
            CP_ASYNC16(abase + soff, ag + (size_t)row * K + c * 4);
            CP_ASYNC16(bbase + soff, bg + (size_t)row * K + c * 4);
        }
    };

#pragma unroll
    for (int j = 0; j < GSTAGES - 1; j++) { load_chunk(j); CP_COMMIT(); }

    for (int j = 0; j < nchunks; j++) {
        CP_WAIT(GSTAGES - 2);
        __syncthreads();
        int pf = j + GSTAGES - 1;
        if (pf < nchunks) load_chunk(pf);
        CP_COMMIT();

        const int stage = j % GSTAGES;
        const float* as = smf + stage * GSTAGE_FLOATS;
        const float* bs = as + GBM * GSTRIDE;

#pragma unroll
        for (int ks = 0; ks < 2; ks++) {
            const int k0 = ks * 8;
            uint32_t afr[4][4], bfr[4][2];
#pragma unroll
            for (int mt = 0; mt < 4; mt++) {
                const uint32_t* ap = (const uint32_t*)(as + (wm0 + mt * 16 + g) * GSTRIDE + k0 + tig);
                afr[mt][0] = ap[0];
                afr[mt][1] = ap[8 * GSTRIDE];
                afr[mt][2] = ap[4];
                afr[mt][3] = ap[8 * GSTRIDE + 4];
            }
#pragma unroll
            for (int nt = 0; nt < 4; nt++) {
                const uint32_t* bp = (const uint32_t*)(bs + (wn0 + nt * 8 + g) * GSTRIDE + k0 + tig);
                bfr[nt][0] = bp[0];
                bfr[nt][1] = bp[4];
            }
#pragma unroll
            for (int mt = 0; mt < 4; mt++)
#pragma unroll
                for (int nt = 0; nt < 4; nt++)
                    mma_tf32(acc[mt * 4 + nt], afr[mt], bfr[nt]);
        }
        __syncthreads();
    }

#pragma unroll
    for (int mt = 0; mt < 4; mt++) {
#pragma unroll
        for (int nt = 0; nt < 4; nt++) {
            int row = m0 + wm0 + mt * 16 + g;
            int col = n0 + wn0 + nt * 8 + tig * 2;
            float2 lo = { acc[mt * 4 + nt][0], acc[mt * 4 + nt][1] };
            float2 hi = { acc[mt * 4 + nt][2], acc[mt * 4 + nt][3] };
            *(float2*)(C + (size_t)row * N + col) = lo;
            *(float2*)(C + (size_t)(row + 8) * N + col) = hi;
        }
    }
}

// ---------------- RoPE on a column-slice of the fused qkv buffer ------------
__global__ void rope_kernel(float* __restrict__ X, int rowstride, int coloff,
                            int nh, int total)
{
    int idx = blockIdx.x * blockDim.x + threadIdx.x;
    if (idx >= total) return;
    int j = idx & 63;
    int rest = idx >> 6;
    int hh = rest % nh;
    int row = rest / nh;
    int t = row & (T_ - 1);

    float inv = 1.0f / powf(10000.0f, (float)j * (1.0f / 64.0f));
    float ang = (float)t * inv;
    float s, c;
    sincosf(ang, &s, &c);

    float* p = X + (size_t)row * rowstride + coloff + hh * D_ + 2 * j;
    float x0 = p[0], x1 = p[1];
    p[0] = tf32r(x0 * c - x1 * s);
    p[1] = tf32r(x0 * s + x1 * c);
}

// ---------------- Flash attention (causal, GQA), Br=128, warp-private -------
// grid (T/128, H, B), 256 threads = 8 warps; warp owns 16 q-rows end-to-end.
// No S smem; softmax in registers; P->A-frag via lane shuffles.
#define FSTR 132
#define F_QS 0
#define F_KS (128 * FSTR)                     // 2 stages of 64x132
#define F_VS (F_KS + 2 * 64 * FSTR)           // 2 stages of 64x132
#define FLASH_SMEM_FLOATS (F_VS + 2 * 64 * FSTR)   // 50688 -> 202752 B

__global__ void __launch_bounds__(256, 1) flash_attn_kernel(
    const float* __restrict__ QKV, float* __restrict__ O)
{
    extern __shared__ float sm[];
    float* Qs = sm + F_QS;
    float* Ks0 = sm + F_KS;
    float* Vs0 = sm + F_VS;
    const uint32_t smem_base = smem_u32(sm);

    const int tid = threadIdx.x;
    const int wid = tid >> 5, lid = tid & 31;
    const int g = lid >> 2, tig = lid & 3;
    const int qt = gridDim.x - 1 - blockIdx.x;     // heavy tiles first
    const int h = blockIdx.y, b = blockIdx.z;
    const int kvh = h >> 1;
    const int q0 = qt * 128;
    const int wr = wid * 16;                       // this warp's rows

    const float* Qg = QKV + (size_t)h * D_;
    const float* Kq = QKV + H_ * D_ + (size_t)kvh * D_;
    const float* Vq = QKV + VOFF + (size_t)kvh * D_;

    // prefetch K,V tile kt into stage kt&1 (64 rows x 32 float4 each)
    auto prefetch_kv = [&](int kt) {
        const int stage = kt & 1;
        const uint32_t kb = smem_base + (uint32_t)(F_KS + stage * 64 * FSTR) * 4;
        const uint32_t vb = smem_base + (uint32_t)(F_VS + stage * 64 * FSTR) * 4;
#pragma unroll
        for (int i = 0; i < 8; i++) {
            int f = i * 256 + tid;
            int row = f >> 5, c16 = f & 31;
            size_t goff = (size_t)(b * T_ + kt * 64 + row) * QKVN + c16 * 4;
            uint32_t soff = (uint32_t)(row * FSTR + c16 * 4) * 4;
            CP_ASYNC16(kb + soff, Kq + goff);
            CP_ASYNC16(vb + soff, Vq + goff);
        }
    };

    // load Q tile: 128 rows x 32 float4
    {
#pragma unroll
        for (int i = 0; i < 16; i++) {
            int f = i * 256 + tid;
            int row = f >> 5, c = f & 31;
            const float4* src = (const float4*)(Qg + (size_t)(b * T_ + q0 + row) * QKVN) + c;
            *((float4*)(Qs + row * FSTR) + c) = *src;
        }
    }

    prefetch_kv(0);
    CP_COMMIT();

    float oacc[16][4];
#pragma unroll
    for (int i = 0; i < 16; i++)
#pragma unroll
        for (int jj = 0; jj < 4; jj++) oacc[i][jj] = 0.f;
    float m0 = -INFINITY, m1 = -INFINITY, l0 = 0.f, l1 = 0.f;

    const float scale = 0.08838834764831845f;
    const int last = 2 * qt + 1;
    const int srcA = (lid & ~3) | (tig >> 1);
    const int srcB = (lid & ~3) | (2 + (tig >> 1));
    const bool selb = (tig & 1);

    for (int kt = 0; kt <= last; kt++) {
        CP_WAIT(0);
        __syncthreads();             // kv(kt) visible; all warps past PV(kt-1)
        if (kt < last) { prefetch_kv(kt + 1); CP_COMMIT(); }

        const float* ks = Ks0 + (kt & 1) * 64 * FSTR;
        const float* vs = Vs0 + (kt & 1) * 64 * FSTR;

        // ---- QK^T: warp tile 16x64, K=128 in 16 ksteps
        float sacc[8][4];
#pragma unroll
        for (int nt = 0; nt < 8; nt++)
#pragma unroll
            for (int jj = 0; jj < 4; jj++) sacc[nt][jj] = 0.f;

#pragma unroll
        for (int ksi = 0; ksi < 16; ksi++) {
            const int k0 = ksi * 8;
            uint32_t a[4];
            const uint32_t* ap = (const uint32_t*)(Qs + (wr + g) * FSTR + k0 + tig);
            a[0] = ap[0];
            a[1] = ap[8 * FSTR];
            a[2] = ap[4];
            a[3] = ap[8 * FSTR + 4];
#pragma unroll
            for (int nt = 0; nt < 8; nt++) {
                uint32_t bb[2];
                const uint32_t* bp = (const uint32_t*)(ks + (nt * 8 + g) * FSTR + k0 + tig);
                bb[0] = bp[0];
                bb[1] = bp[4];
                mma_tf32(sacc[nt], a, bb);
            }
        }

        // ---- scale + causal mask (registers)
        {
            const int r0 = wr + g, r1 = wr + g + 8;       // local q rows
            const int koff = (kt - 2 * qt) * 64;          // k col offset rel. q rows
            const bool diag = (kt >= 2 * qt);
#pragma unroll
            for (int nt = 0; nt < 8; nt++) {
                int j0 = nt * 8 + 2 * tig;
                sacc[nt][0] *= scale;
                sacc[nt][1] *= scale;
                sacc[nt][2] *= scale;
                sacc[nt][3] *= scale;
                if (diag) {
                    if (koff + j0     > r0) sacc[nt][0] = -1e30f;
                    if (koff + j0 + 1 > r0) sacc[nt][1] = -1e30f;
                    if (koff + j0     > r1) sacc[nt][2] = -1e30f;
                    if (koff + j0 + 1 > r1) sacc[nt][3] = -1e30f;
                }
            }
        }

        // ---- warp-private online softmax (rows wr+g, wr+g+8)
        {
            float mx0 = -INFINITY, mx1 = -INFINITY;
#pragma unroll
            for (int nt = 0; nt < 8; nt++) {
                mx0 = fmaxf(mx0, fmaxf(sacc[nt][0], sacc[nt][1]));
                mx1 = fmaxf(mx1, fmaxf(sacc[nt][2], sacc[nt][3]));
            }
            mx0 = fmaxf(mx0, __shfl_xor_sync(0xFFFFFFFF, mx0, 1));
            mx0 = fmaxf(mx0, __shfl_xor_sync(0xFFFFFFFF, mx0, 2));
            mx1 = fmaxf(mx1, __shfl_xor_sync(0xFFFFFFFF, mx1, 1));
            mx1 = fmaxf(mx1, __shfl_xor_sync(0xFFFFFFFF, mx1, 2));
            mx0 = fmaxf(mx0, m0);
            mx1 = fmaxf(mx1, m1);
            float sum0 = 0.f, sum1 = 0.f;
#pragma unroll
            for (int nt = 0; nt < 8; nt++) {
                float p0 = tf32r(__expf(sacc[nt][0] - mx0));
                float p1 = tf32r(__expf(sacc[nt][1] - mx0));
                float p2 = tf32r(__expf(sacc[nt][2] - mx1));
                float p3 = tf32r(__expf(sacc[nt][3] - mx1));
                sacc[nt][0] = p0; sacc[nt][1] = p1;
                sacc[nt][2] = p2; sacc[nt][3] = p3;
                sum0 += p0 + p1;
                sum1 += p2 + p3;
            }
            sum0 += __shfl_xor_sync(0xFFFFFFFF, sum0, 1);
            sum0 += __shfl_xor_sync(0xFFFFFFFF, sum0, 2);
            sum1 += __shfl_xor_sync(0xFFFFFFFF, sum1, 1);
            sum1 += __shfl_xor_sync(0xFFFFFFFF, sum1, 2);
            float al0 = __expf(m0 - mx0);
            float al1 = __expf(m1 - mx1);
            l0 = l0 * al0 + sum0;
            l1 = l1 * al1 + sum1;
            m0 = mx0; m1 = mx1;
#pragma unroll
            for (int nt = 0; nt < 16; nt++) {
                oacc[nt][0] *= al0; oacc[nt][1] *= al0;
                oacc[nt][2] *= al1; oacc[nt][3] *= al1;
            }
        }

        // ---- PV: warp tile 16x128, K=64 in 8 ksteps; A-frags via shuffles
#pragma unroll
        for (int ksi = 0; ksi < 8; ksi++) {
            const int k0 = ksi * 8;
            uint32_t a[4];
            {
                float v00 = __shfl_sync(0xFFFFFFFF, sacc[ksi][0], srcA);
                float v01 = __shfl_sync(0xFFFFFFFF, sacc[ksi][1], srcA);
                float v10 = __shfl_sync(0xFFFFFFFF, sacc[ksi][2], srcA);
                float v11 = __shfl_sync(0xFFFFFFFF, sacc[ksi][3], srcA);
                float w00 = __shfl_sync(0xFFFFFFFF, sacc[ksi][0], srcB);
                float w01 = __shfl_sync(0xFFFFFFFF, sacc[ksi][1], srcB);
                float w10 = __shfl_sync(0xFFFFFFFF, sacc[ksi][2], srcB);
                float w11 = __shfl_sync(0xFFFFFFFF, sacc[ksi][3], srcB);
                a[0] = __float_as_uint(selb ? v01 : v00);
                a[1] = __float_as_uint(selb ? v11 : v10);
                a[2] = __float_as_uint(selb ? w01 : w00);
                a[3] = __float_as_uint(selb ? w11 : w10);
            }
            const uint32_t* vp = (const uint32_t*)(vs + (k0 + tig) * FSTR);
#pragma unroll
            for (int nt = 0; nt < 16; nt++) {
                int col = nt * 8 + g;
                uint32_t bb[2];
                bb[0] = vp[col];
                bb[1] = vp[4 * FSTR + col];
                mma_tf32(oacc[nt], a, bb);
            }
        }
    }

    // epilogue
    {
        float il0 = 1.f / l0;
        float il1 = 1.f / l1;
        float* O0 = O + (size_t)(b * T_ + q0 + wr + g) * (H_ * D_) + h * D_;
        float* O1 = O + (size_t)(b * T_ + q0 + wr + g + 8) * (H_ * D_) + h * D_;
#pragma unroll
        for (int nt = 0; nt < 16; nt++) {
            int col = nt * 8 + 2 * tig;
            *(float2*)(O0 + col) = make_float2(tf32r(oacc[nt][0] * il0), tf32r(oacc[nt][1] * il0));
            *(float2*)(O1 + col) = make_float2(tf32r(oacc[nt][2] * il1), tf32r(oacc[nt][3] * il1));
        }
    }
}

// -------------------------------- launch -------------------------------------
extern "C" void kernel_launch(void* const* d_in, const int* in_sizes, int n_in,
                              void* d_out, int out_size)
{
    const float* x  = (const float*)d_in[0];
    const float* wq = (const float*)d_in[2];
    const float* wk = (const float*)d_in[3];
    const float* wv = (const float*)d_in[4];
    const float* wo = (const float*)d_in[5];
    float* out = (float*)d_out;

    float *qkv, *o, *xr, *wqkvt, *wot;
    cudaGetSymbolAddress((void**)&qkv, g_qkv);
    cudaGetSymbolAddress((void**)&o, g_o);
    cudaGetSymbolAddress((void**)&xr, g_xr);
    cudaGetSymbolAddress((void**)&wqkvt, g_wqkvt);
    cudaGetSymbolAddress((void**)&wot, g_wot);

    dim3 tb(32, 8);
    round_tf32_kernel<<<(ROWS_ * E_ / 4 + 255) / 256, 256>>>(x, xr, ROWS_ * E_ / 4);
    transpose_kernel<<<dim3((H_ * D_) / 32, E_ / 32), tb>>>(
        wq, wqkvt, E_, H_ * D_);
    transpose_kernel<<<dim3((KVH_ * D_) / 32, E_ / 32), tb>>>(
        wk, wqkvt + (size_t)(H_ * D_) * E_, E_, KVH_ * D_);
    transpose_kernel<<<dim3((KVH_ * D_) / 32, E_ / 32), tb>>>(
        wv, wqkvt + (size_t)(H_ * D_ + KVH_ * D_) * E_, E_, KVH_ * D_);

    cudaFuncSetAttribute(tc_gemm_kernel,
                         cudaFuncAttributeMaxDynamicSharedMemorySize, GSMEM_BYTES);

    // Fused QKV projection: [4096, 2048] @ [2048, 4096]
    tc_gemm_kernel<<<dim3(QKVN / 128, ROWS_ / 128), 256, GSMEM_BYTES>>>(
        ROWS_, QKVN, E_, xr, wqkvt, qkv);

    // RoPE on q and k slices; round v slice to tf32
    {
        int total_q = ROWS_ * H_ * 64;
        int total_k = ROWS_ * KVH_ * 64;
        rope_kernel<<<(total_q + 255) / 256, 256>>>(qkv, QKVN, 0, H_, total_q);
        rope_kernel<<<(total_k + 255) / 256, 256>>>(qkv, QKVN, H_ * D_, KVH_, total_k);
        vround_kernel<<<(ROWS_ * 256) / 256, 256>>>(qkv);
    }

    // Flash attention (Br=128)
    {
        int smem_bytes = FLASH_SMEM_FLOATS * (int)sizeof(float);
        cudaFuncSetAttribute(flash_attn_kernel,
                             cudaFuncAttributeMaxDynamicSharedMemorySize, smem_bytes);
        flash_attn_kernel<<<dim3(T_ / 128, H_, B_), 256, smem_bytes>>>(qkv, o);
    }

    // wo transpose + output projection
    transpose_kernel<<<dim3(E_ / 32, (H_ * D_) / 32), tb>>>(wo, wot, H_ * D_, E_);
    tc_gemm_kernel<<<dim3(E_ / 128, ROWS_ / 128), 256, GSMEM_BYTES>>>(
        ROWS_, E_, H_ * D_, o, wot, out);
}

// round 10
// speedup vs baseline: 7.3778x; 1.1096x over previous
#include <cuda_runtime.h>
#include <cuda_bf16.h>
#include <math.h>
#include <cstdint>

// Problem constants
#define B_  2
#define T_  2048
#define E_  2048
#define H_  16
#define KVH_ 8
#define D_  128
#define ROWS_ (B_ * T_)            // 4096
#define QKVN (H_ * D_ + 2 * KVH_ * D_)   // 4096 fused N
#define VOFF (H_ * D_ + KVH_ * D_)       // 3072: v column offset in fused buffer

// ---------------- scratch (device globals; no allocs allowed) ----------------
__device__ float g_qkv[(size_t)ROWS_ * QKVN];      // fused q|k|v
__device__ float g_o[(size_t)ROWS_ * H_ * D_];     // attn out
__device__ float g_xr[(size_t)ROWS_ * E_];         // tf32-rounded x
__device__ float g_wqkvt[(size_t)QKVN * E_];       // [wq|wk|wv]^T rows, tf32
__device__ float g_wot[(size_t)E_ * H_ * D_];

// ====================== helpers ======================
__device__ __forceinline__ uint32_t smem_u32(const void* p) {
    uint32_t a;
    asm("{ .reg .u64 t; cvta.to.shared.u64 t, %1; cvt.u32.u64 %0, t; }" : "=r"(a) : "l"(p));
    return a;
}
#define CP_ASYNC16(dst, src) \
    asm volatile("cp.async.cg.shared.global [%0], [%1], 16;" :: "r"(dst), "l"(src))
#define CP_COMMIT() asm volatile("cp.async.commit_group;" ::: "memory")
#define CP_WAIT(n)  asm volatile("cp.async.wait_group %0;" :: "n"(n) : "memory")

__device__ __forceinline__ uint32_t f2tf32(float x) {
    uint32_t u;
    asm("cvt.rna.tf32.f32 %0, %1;" : "=r"(u) : "f"(x));
    return u;
}
__device__ __forceinline__ float tf32r(float x) {
    return __uint_as_float(f2tf32(x));
}
__device__ __forceinline__ void mma_tf32(float (&c)[4], const uint32_t (&a)[4],
                                         const uint32_t (&b)[2]) {
    asm volatile(
        "mma.sync.aligned.m16n8k8.row.col.f32.tf32.tf32.f32 "
        "{%0,%1,%2,%3}, {%4,%5,%6,%7}, {%8,%9}, {%0,%1,%2,%3};"
        : "+f"(c[0]), "+f"(c[1]), "+f"(c[2]), "+f"(c[3])
        : "r"(a[0]), "r"(a[1]), "r"(a[2]), "r"(a[3]), "r"(b[0]), "r"(b[1]));
}

// ============== round x to tf32 ==============
__global__ void round_tf32_kernel(const float* __restrict__ in, float* __restrict__ out,
                                  int n4)
{
    int i = blockIdx.x * blockDim.x + threadIdx.x;
    if (i >= n4) return;
    float4 t = ((const float4*)in)[i];
    t.x = tf32r(t.x); t.y = tf32r(t.y); t.z = tf32r(t.z); t.w = tf32r(t.w);
    ((float4*)out)[i] = t;
}

// ============== round v-slice of fused qkv buffer to tf32 (in place) ==========
__global__ void vround_kernel(float* __restrict__ X)
{
    int idx = blockIdx.x * blockDim.x + threadIdx.x;
    int row = idx >> 8, c4 = idx & 255;
    float4* p = (float4*)(X + (size_t)row * QKVN + VOFF) + c4;
    float4 t = *p;
    t.x = tf32r(t.x); t.y = tf32r(t.y); t.z = tf32r(t.z); t.w = tf32r(t.w);
    *p = t;
}

// ============ fused qkv weight transpose: one launch for wq|wk|wv ============
__global__ void transpose_qkv_kernel(const float* __restrict__ Wq,
                                     const float* __restrict__ Wk,
                                     const float* __restrict__ Wv,
                                     float* __restrict__ Wt)
{
    __shared__ float tile[32][33];
    int z = blockIdx.z;
    const float* W = (z == 0) ? Wq : (z == 1) ? Wk : Wv;
    int N = (z == 0) ? (H_ * D_) : (KVH_ * D_);
    int rowoff = (z == 0) ? 0 : (z == 1) ? (H_ * D_) : (H_ * D_ + KVH_ * D_);
    int bx = blockIdx.x * 32;  // n  (uniform per block -> uniform early return)
    if (bx >= N) return;
    int by = blockIdx.y * 32;  // k
    int tx = threadIdx.x, ty = threadIdx.y;
#pragma unroll
    for (int j = 0; j < 32; j += 8)
        tile[ty + j][tx] = W[(size_t)(by + ty + j) * N + bx + tx];
    __syncthreads();
#pragma unroll
    for (int j = 0; j < 32; j += 8)
        Wt[(size_t)(rowoff + bx + ty + j) * E_ + by + tx] = tf32r(tile[tx][ty + j]);
}

// ============ generic weight transpose (wo): Wt[N,K] = tf32(W[K,N]) ==========
__global__ void transpose_kernel(const float* __restrict__ W, float* __restrict__ Wt,
                                 int K, int N)
{
    __shared__ float tile[32][33];
    int bx = blockIdx.x * 32;  // n
    int by = blockIdx.y * 32;  // k
    int tx = threadIdx.x, ty = threadIdx.y;
#pragma unroll
    for (int j = 0; j < 32; j += 8)
        tile[ty + j][tx] = W[(size_t)(by + ty + j) * N + bx + tx];
    __syncthreads();
#pragma unroll
    for (int j = 0; j < 32; j += 8)
        Wt[(size_t)(bx + ty + j) * K + by + tx] = tf32r(tile[tx][ty + j]);
}

// ====================== tf32 mma.sync GEMM ======================
// C[M,N] = A[M,K] @ Bt[N,K]^T.  CTA tile 128x128, BK=32, 2-stage cp.async,
// 2 CTAs/SM. 256 threads = 8 warps; warp tile 64x32.
#define GBM 128
#define GBN 128
#define GBK 32
#define GSTRIDE 36                           // 32 + 4 pad (banks: 36 = 4 mod 32)
#define GSTAGE_FLOATS (2 * GBM * GSTRIDE)    // A tile + B tile
#define GSTAGES 2
#define GSMEM_BYTES (GSTAGES * GSTAGE_FLOATS * 4)   // 73728

__global__ void __launch_bounds__(256, 2) tc_gemm_kernel(
    int M, int N, int K,
    const float* __restrict__ A, const float* __restrict__ Bt,
    float* __restrict__ C)
{
    extern __shared__ float smf[];
    const uint32_t smem_base = smem_u32(smf);
    const int tid = threadIdx.x;
    const int wid = tid >> 5, lid = tid & 31;
    const int g = lid >> 2, tig = lid & 3;

    const int m0 = blockIdx.y * GBM;
    const int n0 = blockIdx.x * GBN;
    const float* Ab = A  + (size_t)m0 * K;
    const float* Bb = Bt + (size_t)n0 * K;
    const int nchunks = K / GBK;

    const int wm0 = (wid >> 2) * 64;
    const int wn0 = (wid & 3) * 32;

    float acc[16][4];
#pragma unroll
    for (int i = 0; i < 16; i++)
#pragma unroll
        for (int jj = 0; jj < 4; jj++) acc[i][jj] = 0.f;

    auto load_chunk = [&](int j) {
        const int stage = j & 1;
        const uint32_t abase = smem_base + stage * GSTAGE_FLOATS * 4;
        const uint32_t bbase = abase + GBM * GSTRIDE * 4;
        const float* ag = Ab + j * GBK;
        const float* bg = Bb + j * GBK;
#pragma unroll
        for (int i = 0; i < 4; i++) {
            int f = i * 256 + tid;            // 0..1023
            int row = f >> 3, c = f & 7;      // c in 16B units (0..7)
            uint32_t soff = (uint32_t)(row * GSTRIDE + c * 4) * 4;
            CP_ASYNC16(abase + soff, ag + (size_t)row * K + c * 4);
            CP_ASYNC16(bbase + soff, bg + (size_t)row * K + c * 4);
        }
    };

    load_chunk(0);
    CP_COMMIT();

    for (int j = 0; j < nchunks; j++) {
        CP_WAIT(0);                  // chunk j resident
        __syncthreads();
        if (j + 1 < nchunks) { load_chunk(j + 1); CP_COMMIT(); }

        const float* as = smf + (j & 1) * GSTAGE_FLOATS;
        const float* bs = as + GBM * GSTRIDE;

#pragma unroll
        for (int ks = 0; ks < 4; ks++) {
            const int k0 = ks * 8;
            uint32_t afr[4][4], bfr[4][2];
#pragma unroll
            for (int mt = 0; mt < 4; mt++) {
                const uint32_t* ap = (const uint32_t*)(as + (wm0 + mt * 16 + g) * GSTRIDE + k0 + tig);
                afr[mt][0] = ap[0];
                afr[mt][1] = ap[8 * GSTRIDE];
                afr[mt][2] = ap[4];
                afr[mt][3] = ap[8 * GSTRIDE + 4];
            }
#pragma unroll
            for (int nt = 0; nt < 4; nt++) {
                const uint32_t* bp = (const uint32_t*)(bs + (wn0 + nt * 8 + g) * GSTRIDE + k0 + tig);
                bfr[nt][0] = bp[0];
                bfr[nt][1] = bp[4];
            }
#pragma unroll
            for (int mt = 0; mt < 4; mt++)
#pragma unroll
                for (int nt = 0; nt < 4; nt++)
                    mma_tf32(acc[mt * 4 + nt], afr[mt], bfr[nt]);
        }
        __syncthreads();
    }

#pragma unroll
    for (int mt = 0; mt < 4; mt++) {
#pragma unroll
        for (int nt = 0; nt < 4; nt++) {
            int row = m0 + wm0 + mt * 16 + g;
            int col = n0 + wn0 + nt * 8 + tig * 2;
            float2 lo = { acc[mt * 4 + nt][0], acc[mt * 4 + nt][1] };
            float2 hi = { acc[mt * 4 + nt][2], acc[mt * 4 + nt][3] };
            *(float2*)(C + (size_t)row * N + col) = lo;
            *(float2*)(C + (size_t)(row + 8) * N + col) = hi;
        }
    }
}

// ---------------- RoPE on a column-slice of the fused qkv buffer ------------
__global__ void rope_kernel(float* __restrict__ X, int rowstride, int coloff,
                            int nh, int total)
{
    int idx = blockIdx.x * blockDim.x + threadIdx.x;
    if (idx >= total) return;
    int j = idx & 63;
    int rest = idx >> 6;
    int hh = rest % nh;
    int row = rest / nh;
    int t = row & (T_ - 1);

    float inv = 1.0f / powf(10000.0f, (float)j * (1.0f / 64.0f));
    float ang = (float)t * inv;
    float s, c;
    sincosf(ang, &s, &c);

    float* p = X + (size_t)row * rowstride + coloff + hh * D_ + 2 * j;
    float x0 = p[0], x1 = p[1];
    p[0] = tf32r(x0 * c - x1 * s);
    p[1] = tf32r(x0 * s + x1 * c);
}

// ---------------- Flash attention (causal, GQA), Br=128, warp-private -------
#define FSTR 132
#define F_QS 0
#define F_KS (128 * FSTR)                     // 2 stages of 64x132
#define F_VS (F_KS + 2 * 64 * FSTR)           // 2 stages of 64x132
#define FLASH_SMEM_FLOATS (F_VS + 2 * 64 * FSTR)   // 50688 -> 202752 B

__global__ void __launch_bounds__(256, 1) flash_attn_kernel(
    const float* __restrict__ QKV, float* __restrict__ O)
{
    extern __shared__ float sm[];
    float* Qs = sm + F_QS;
    float* Ks0 = sm + F_KS;
    float* Vs0 = sm + F_VS;
    const uint32_t smem_base = smem_u32(sm);

    const int tid = threadIdx.x;
    const int wid = tid >> 5, lid = tid & 31;
    const int g = lid >> 2, tig = lid & 3;
    const int qt = gridDim.x - 1 - blockIdx.x;     // heavy tiles first
    const int h = blockIdx.y, b = blockIdx.z;
    const int kvh = h >> 1;
    const int q0 = qt * 128;
    const int wr = wid * 16;

    const float* Qg = QKV + (size_t)h * D_;
    const float* Kq = QKV + H_ * D_ + (size_t)kvh * D_;
    const float* Vq = QKV + VOFF + (size_t)kvh * D_;

    auto prefetch_kv = [&](int kt) {
        const int stage = kt & 1;
        const uint32_t kb = smem_base + (uint32_t)(F_KS + stage * 64 * FSTR) * 4;
        const uint32_t vb = smem_base + (uint32_t)(F_VS + stage * 64 * FSTR) * 4;
#pragma unroll
        for (int i = 0; i < 8; i++) {
            int f = i * 256 + tid;
            int row = f >> 5, c16 = f & 31;
            size_t goff = (size_t)(b * T_ + kt * 64 + row) * QKVN + c16 * 4;
            uint32_t soff = (uint32_t)(row * FSTR + c16 * 4) * 4;
            CP_ASYNC16(kb + soff, Kq + goff);
            CP_ASYNC16(vb + soff, Vq + goff);
        }
    };

    {
#pragma unroll
        for (int i = 0; i < 16; i++) {
            int f = i * 256 + tid;
            int row = f >> 5, c = f & 31;
            const float4* src = (const float4*)(Qg + (size_t)(b * T_ + q0 + row) * QKVN) + c;
            *((float4*)(Qs + row * FSTR) + c) = *src;
        }
    }

    prefetch_kv(0);
    CP_COMMIT();

    float oacc[16][4];
#pragma unroll
    for (int i = 0; i < 16; i++)
#pragma unroll
        for (int jj = 0; jj < 4; jj++) oacc[i][jj] = 0.f;
    float m0 = -INFINITY, m1 = -INFINITY, l0 = 0.f, l1 = 0.f;

    const float scale = 0.08838834764831845f;
    const int last = 2 * qt + 1;
    const int srcA = (lid & ~3) | (tig >> 1);
    const int srcB = (lid & ~3) | (2 + (tig >> 1));
    const bool selb = (tig & 1);

    for (int kt = 0; kt <= last; kt++) {
        CP_WAIT(0);
        __syncthreads();
        if (kt < last) { prefetch_kv(kt + 1); CP_COMMIT(); }

        const float* ks = Ks0 + (kt & 1) * 64 * FSTR;
        const float* vs = Vs0 + (kt & 1) * 64 * FSTR;

        float sacc[8][4];
#pragma unroll
        for (int nt = 0; nt < 8; nt++)
#pragma unroll
            for (int jj = 0; jj < 4; jj++) sacc[nt][jj] = 0.f;

#pragma unroll
        for (int ksi = 0; ksi < 16; ksi++) {
            const int k0 = ksi * 8;
            uint32_t a[4];
            const uint32_t* ap = (const uint32_t*)(Qs + (wr + g) * FSTR + k0 + tig);
            a[0] = ap[0];
            a[1] = ap[8 * FSTR];
            a[2] = ap[4];
            a[3] = ap[8 * FSTR + 4];
#pragma unroll
            for (int nt = 0; nt < 8; nt++) {
                uint32_t bb[2];
                const uint32_t* bp = (const uint32_t*)(ks + (nt * 8 + g) * FSTR + k0 + tig);
                bb[0] = bp[0];
                bb[1] = bp[4];
                mma_tf32(sacc[nt], a, bb);
            }
        }

        {
            const int r0 = wr + g, r1 = wr + g + 8;
            const int koff = (kt - 2 * qt) * 64;
            const bool diag = (kt >= 2 * qt);
#pragma unroll
            for (int nt = 0; nt < 8; nt++) {
                int j0 = nt * 8 + 2 * tig;
                sacc[nt][0] *= scale;
                sacc[nt][1] *= scale;
                sacc[nt][2] *= scale;
                sacc[nt][3] *= scale;
                if (diag) {
                    if (koff + j0     > r0) sacc[nt][0] = -1e30f;
                    if (koff + j0 + 1 > r0) sacc[nt][1] = -1e30f;
                    if (koff + j0     > r1) sacc[nt][2] = -1e30f;
                    if (koff + j0 + 1 > r1) sacc[nt][3] = -1e30f;
                }
            }
        }

        {
            float mx0 = -INFINITY, mx1 = -INFINITY;
#pragma unroll
            for (int nt = 0; nt < 8; nt++) {
                mx0 = fmaxf(mx0, fmaxf(sacc[nt][0], sacc[nt][1]));
                mx1 = fmaxf(mx1, fmaxf(sacc[nt][2], sacc[nt][3]));
            }
            mx0 = fmaxf(mx0, __shfl_xor_sync(0xFFFFFFFF, mx0, 1));
            mx0 = fmaxf(mx0, __shfl_xor_sync(0xFFFFFFFF, mx0, 2));
            mx1 = fmaxf(mx1, __shfl_xor_sync(0xFFFFFFFF, mx1, 1));
            mx1 = fmaxf(mx1, __shfl_xor_sync(0xFFFFFFFF, mx1, 2));
            mx0 = fmaxf(mx0, m0);
            mx1 = fmaxf(mx1, m1);
            float sum0 = 0.f, sum1 = 0.f;
#pragma unroll
            for (int nt = 0; nt < 8; nt++) {
                float p0 = tf32r(__expf(sacc[nt][0] - mx0));
                float p1 = tf32r(__expf(sacc[nt][1] - mx0));
                float p2 = tf32r(__expf(sacc[nt][2] - mx1));
                float p3 = tf32r(__expf(sacc[nt][3] - mx1));
                sacc[nt][0] = p0; sacc[nt][1] = p1;
                sacc[nt][2] = p2; sacc[nt][3] = p3;
                sum0 += p0 + p1;
                sum1 += p2 + p3;
            }
            sum0 += __shfl_xor_sync(0xFFFFFFFF, sum0, 1);
            sum0 += __shfl_xor_sync(0xFFFFFFFF, sum0, 2);
            sum1 += __shfl_xor_sync(0xFFFFFFFF, sum1, 1);
            sum1 += __shfl_xor_sync(0xFFFFFFFF, sum1, 2);
            float al0 = __expf(m0 - mx0);
            float al1 = __expf(m1 - mx1);
            l0 = l0 * al0 + sum0;
            l1 = l1 * al1 + sum1;
            m0 = mx0; m1 = mx1;
#pragma unroll
            for (int nt = 0; nt < 16; nt++) {
                oacc[nt][0] *= al0; oacc[nt][1] *= al0;
                oacc[nt][2] *= al1; oacc[nt][3] *= al1;
            }
        }

#pragma unroll
        for (int ksi = 0; ksi < 8; ksi++) {
            const int k0 = ksi * 8;
            uint32_t a[4];
            {
                float v00 = __shfl_sync(0xFFFFFFFF, sacc[ksi][0], srcA);
                float v01 = __shfl_sync(0xFFFFFFFF, sacc[ksi][1], srcA);
                float v10 = __shfl_sync(0xFFFFFFFF, sacc[ksi][2], srcA);
                float v11 = __shfl_sync(0xFFFFFFFF, sacc[ksi][3], srcA);
                float w00 = __shfl_sync(0xFFFFFFFF, sacc[ksi][0], srcB);
                float w01 = __shfl_sync(0xFFFFFFFF, sacc[ksi][1], srcB);
                float w10 = __shfl_sync(0xFFFFFFFF, sacc[ksi][2], srcB);
                float w11 = __shfl_sync(0xFFFFFFFF, sacc[ksi][3], srcB);
                a[0] = __float_as_uint(selb ? v01 : v00);
                a[1] = __float_as_uint(selb ? v11 : v10);
                a[2] = __float_as_uint(selb ? w01 : w00);
                a[3] = __float_as_uint(selb ? w11 : w10);
            }
            const uint32_t* vp = (const uint32_t*)(vs + (k0 + tig) * FSTR);
#pragma unroll
            for (int nt = 0; nt < 16; nt++) {
                int col = nt * 8 + g;
                uint32_t bb[2];
                bb[0] = vp[col];
                bb[1] = vp[4 * FSTR + col];
                mma_tf32(oacc[nt], a, bb);
            }
        }
    }

    {
        float il0 = 1.f / l0;
        float il1 = 1.f / l1;
        float* O0 = O + (size_t)(b * T_ + q0 + wr + g) * (H_ * D_) + h * D_;
        float* O1 = O + (size_t)(b * T_ + q0 + wr + g + 8) * (H_ * D_) + h * D_;
#pragma unroll
        for (int nt = 0; nt < 16; nt++) {
            int col = nt * 8 + 2 * tig;
            *(float2*)(O0 + col) = make_float2(tf32r(oacc[nt][0] * il0), tf32r(oacc[nt][1] * il0));
            *(float2*)(O1 + col) = make_float2(tf32r(oacc[nt][2] * il1), tf32r(oacc[nt][3] * il1));
        }
    }
}

// -------------------------------- launch -------------------------------------
extern "C" void kernel_launch(void* const* d_in, const int* in_sizes, int n_in,
                              void* d_out, int out_size)
{
    const float* x  = (const float*)d_in[0];
    const float* wq = (const float*)d_in[2];
    const float* wk = (const float*)d_in[3];
    const float* wv = (const float*)d_in[4];
    const float* wo = (const float*)d_in[5];
    float* out = (float*)d_out;

    float *qkv, *o, *xr, *wqkvt, *wot;
    cudaGetSymbolAddress((void**)&qkv, g_qkv);
    cudaGetSymbolAddress((void**)&o, g_o);
    cudaGetSymbolAddress((void**)&xr, g_xr);
    cudaGetSymbolAddress((void**)&wqkvt, g_wqkvt);
    cudaGetSymbolAddress((void**)&wot, g_wot);

    dim3 tb(32, 8);
    // launch 0: round x
    round_tf32_kernel<<<(ROWS_ * E_ / 4 + 255) / 256, 256>>>(x, xr, ROWS_ * E_ / 4);
    // launch 1: fused qkv weight transpose
    transpose_qkv_kernel<<<dim3(64, 64, 3), tb>>>(wq, wk, wv, wqkvt);
    // launch 2: wo transpose
    transpose_kernel<<<dim3(E_ / 32, (H_ * D_) / 32), tb>>>(wo, wot, H_ * D_, E_);

    cudaFuncSetAttribute(tc_gemm_kernel,
                         cudaFuncAttributeMaxDynamicSharedMemorySize, GSMEM_BYTES);

    // launch 3 (ncu-captured): fused QKV projection [4096,2048]@[2048,4096]
    tc_gemm_kernel<<<dim3(QKVN / 128, ROWS_ / 128), 256, GSMEM_BYTES>>>(
        ROWS_, QKVN, E_, xr, wqkvt, qkv);

    // RoPE on q and k slices; round v slice to tf32
    {
        int total_q = ROWS_ * H_ * 64;
        int total_k = ROWS_ * KVH_ * 64;
        rope_kernel<<<(total_q + 255) / 256, 256>>>(qkv, QKVN, 0, H_, total_q);
        rope_kernel<<<(total_k + 255) / 256, 256>>>(qkv, QKVN, H_ * D_, KVH_, total_k);
        vround_kernel<<<(ROWS_ * 256) / 256, 256>>>(qkv);
    }

    // Flash attention (Br=128)
    {
        int smem_bytes = FLASH_SMEM_FLOATS * (int)sizeof(float);
        cudaFuncSetAttribute(flash_attn_kernel,
                             cudaFuncAttributeMaxDynamicSharedMemorySize, smem_bytes);
        flash_attn_kernel<<<dim3(T_ / 128, H_, B_), 256, smem_bytes>>>(qkv, o);
    }

    // Output projection
    tc_gemm_kernel<<<dim3(E_ / 128, ROWS_ / 128), 256, GSMEM_BYTES>>>(
        ROWS_, E_, H_ * D_, o, wot, out);
}